// round 12
// baseline (speedup 1.0000x reference)
#include <cuda_runtime.h>
#include <cuda_fp16.h>
#include <cstdint>
#include <cstddef>

// ---------------------------------------------------------------------------
// Problem constants
// ---------------------------------------------------------------------------
#define DIM   4096
#define HID   11008
#define MTOK  4096          // B*S = 2*2048

static constexpr int BK = 64;          // 64 fp16 = 128 bytes per row (SW128 atom)
static constexpr int THREADS = 256;    // 8 warps
static constexpr int STAGES = 3;

// Fused GEMM1+3: CTA 128(m) x 64(n per matrix); stage = A 16K + B1 8K + B3 8K
static constexpr int F_BM = 128;
static constexpr int F_BN = 64;                         // per weight matrix
static constexpr int F_STAGE = (F_BM + 2 * F_BN) * 128; // 32 KB
static constexpr int F_SMEM = STAGES * F_STAGE;         // 96 KB

// GEMM2: CTA 128 x 128, split-K = 2
static constexpr int G_BM = 128;
static constexpr int G_BN = 128;
static constexpr int G_SPLITK = 2;
static constexpr int G_STAGE = (G_BM + G_BN) * 128;     // 32 KB
static constexpr int G_SMEM = STAGES * G_STAGE;         // 96 KB

// ---------------------------------------------------------------------------
// NF4 codebook
// ---------------------------------------------------------------------------
__constant__ float c_nf4[16] = {
    -1.0f, -0.6961928009986877f, -0.5250730514526367f, -0.39491748809814453f,
    -0.28444138169288635f, -0.18477343022823334f, -0.09105003625154495f, 0.0f,
    0.07958029955625534f, 0.16093020141124725f, 0.24611230194568634f,
    0.33791524171829224f, 0.44070982933044434f, 0.5626170039176941f,
    0.6989939212799072f, 1.0f};

// ---------------------------------------------------------------------------
// Static device scratch
// ---------------------------------------------------------------------------
__device__ __align__(256) __half g_w1[(size_t)HID * DIM];
__device__ __align__(256) __half g_w3[(size_t)HID * DIM];
__device__ __align__(256) __half g_w2[(size_t)DIM * HID];
__device__ __align__(256) __half g_x [(size_t)MTOK * DIM];
__device__ __align__(256) __half g_h [(size_t)MTOK * HID];
__device__ __align__(256) float  g_scr[(size_t)MTOK * DIM];   // split-K partial

// ---------------------------------------------------------------------------
// PTX helpers (sm_100 baseline: cp.async, ldmatrix, mma.sync)
// ---------------------------------------------------------------------------
__device__ __forceinline__ uint32_t smem_u32(const void* p) {
    uint32_t r;
    asm("{ .reg .u64 t; cvta.to.shared.u64 t, %1; cvt.u32.u64 %0, t; }"
        : "=r"(r) : "l"(p));
    return r;
}

__device__ __forceinline__ void cp_async16(uint32_t dst, const void* src) {
    asm volatile("cp.async.cg.shared.global [%0], [%1], 16;" :: "r"(dst), "l"(src));
}
__device__ __forceinline__ void cp_async_commit() {
    asm volatile("cp.async.commit_group;" ::: "memory");
}
template <int N>
__device__ __forceinline__ void cp_async_wait() {
    asm volatile("cp.async.wait_group %0;" :: "n"(N) : "memory");
}

__device__ __forceinline__ void ldsm_x4(uint32_t* r, uint32_t addr) {
    asm volatile("ldmatrix.sync.aligned.m8n8.x4.shared.b16 {%0,%1,%2,%3}, [%4];"
                 : "=r"(r[0]), "=r"(r[1]), "=r"(r[2]), "=r"(r[3]) : "r"(addr));
}

__device__ __forceinline__ void mma16816(float* c, const uint32_t* a, const uint32_t* b) {
    asm volatile(
        "mma.sync.aligned.m16n8k16.row.col.f32.f16.f16.f32 "
        "{%0,%1,%2,%3}, {%4,%5,%6,%7}, {%8,%9}, {%0,%1,%2,%3};"
        : "+f"(c[0]), "+f"(c[1]), "+f"(c[2]), "+f"(c[3])
        : "r"(a[0]), "r"(a[1]), "r"(a[2]), "r"(a[3]), "r"(b[0]), "r"(b[1]));
}

__device__ __forceinline__ uint32_t sw128(uint32_t off) {
    return off ^ ((off >> 3) & 0x70);
}

// ---------------------------------------------------------------------------
// Dequant (shfl-LUT, 32 elems/thread) / convert / add kernels
// ---------------------------------------------------------------------------
template <int K>
__global__ void __launch_bounds__(256)
dequant_nf4_kernel(const int* __restrict__ codes, const float* __restrict__ absmax,
                   __half* __restrict__ out, int total) {
    const int t = blockIdx.x * 256 + threadIdx.x;
    const int base = t * 32;                 // 32 codes per thread
    if (base >= total) return;

    // Register LUT: lane i holds nf4[i & 15]; lookup via one shfl.
    const float tbl = c_nf4[threadIdx.x & 15];

    // 32 elems stay inside one 64-wide absmax block (base is 32-aligned).
    const int row = base / K;                // K is a compile-time constant
    const int col = base - row * K;
    const float am = absmax[row * (K >> 6) + (col >> 6)];

    int4 c[8];
#pragma unroll
    for (int i = 0; i < 8; ++i)
        c[i] = reinterpret_cast<const int4*>(codes + base)[i];

    __half2 hs[16];
#pragma unroll
    for (int i = 0; i < 8; ++i) {
        float v0 = __shfl_sync(0xffffffffu, tbl, c[i].x & 15);
        float v1 = __shfl_sync(0xffffffffu, tbl, c[i].y & 15);
        float v2 = __shfl_sync(0xffffffffu, tbl, c[i].z & 15);
        float v3 = __shfl_sync(0xffffffffu, tbl, c[i].w & 15);
        hs[2 * i]     = __floats2half2_rn(v0 * am, v1 * am);
        hs[2 * i + 1] = __floats2half2_rn(v2 * am, v3 * am);
    }
#pragma unroll
    for (int i = 0; i < 4; ++i)
        reinterpret_cast<uint4*>(out + base)[i] =
            reinterpret_cast<const uint4*>(hs)[i];
}

__global__ void __launch_bounds__(256)
convert_x_kernel(const float* __restrict__ x, __half* __restrict__ out, int total) {
    int t = blockIdx.x * 256 + threadIdx.x;
    int base = t * 8;
    if (base >= total) return;
    float4 a = reinterpret_cast<const float4*>(x + base)[0];
    float4 b = reinterpret_cast<const float4*>(x + base)[1];
    __half2 hs[4];
    hs[0] = __floats2half2_rn(a.x, a.y);
    hs[1] = __floats2half2_rn(a.z, a.w);
    hs[2] = __floats2half2_rn(b.x, b.y);
    hs[3] = __floats2half2_rn(b.z, b.w);
    *reinterpret_cast<uint4*>(out + base) = *reinterpret_cast<const uint4*>(hs);
}

__global__ void __launch_bounds__(256)
add_out_kernel(float4* __restrict__ out, const float4* __restrict__ scr, int total4) {
    int t = blockIdx.x * 256 + threadIdx.x;
    if (t < total4) {
        float4 o = out[t];
        float4 s = scr[t];
        out[t] = make_float4(o.x + s.x, o.y + s.y, o.z + s.z, o.w + s.w);
    }
}

// ---------------------------------------------------------------------------
// Fused GEMM1+GEMM3+SwiGLU:  H = silu(x W1^T) * (x W3^T), fp16 out.
// CTA 128m x 64n per matrix; 8 warps (2m x 4n), warp tile 64m x 16n/matrix.
// 3-stage cp.async pipeline, one __syncthreads per k-tile, 2 CTAs/SM.
// Raster: bm-fastest over ALL 32 m-tiles (x stays L2-resident; each weight
// streams from DRAM exactly once).
// ---------------------------------------------------------------------------
__global__ void __launch_bounds__(THREADS, 2)
fused_gemm13_kernel(const __half* __restrict__ A, const __half* __restrict__ B1,
                    const __half* __restrict__ B3, __half* __restrict__ H) {
    extern __shared__ __align__(1024) char smem[];
    const int tid = threadIdx.x;
    const int wid = tid >> 5, lane = tid & 31;
    const uint32_t sb = smem_u32(smem);

    // raster: full-m sweep per n-tile (G = TM = 32)
    const int TM = MTOK / F_BM;  // 32
    const int bid = blockIdx.x;
    const int bm = bid % TM;
    const int bn = bid / TM;
    const int row0 = bm * F_BM, col0 = bn * F_BN;

    const int wm = (wid & 1) * 64;       // warp m offset
    const int wn = (wid >> 1) * 16;      // warp n offset (per weight matrix)

    uint32_t sA[STAGES], sB1[STAGES], sB3[STAGES];
#pragma unroll
    for (int s = 0; s < STAGES; ++s) {
        sA[s]  = sb + s * F_STAGE;
        sB1[s] = sA[s] + F_BM * 128;
        sB3[s] = sB1[s] + F_BN * 128;
    }

    // ---- precomputed cp.async chunk descriptors (loop-invariant) ----
    uint32_t offA[4], offB[2];
    const __half *pA[4], *pB1[2], *pB3[2];
#pragma unroll
    for (int i = 0; i < 4; ++i) {
        int c = tid + i * THREADS;
        int r = c >> 3, cc = c & 7;
        offA[i] = sw128((uint32_t)(r * 128 + cc * 16));
        pA[i] = A + (size_t)(row0 + r) * DIM + cc * 8;
    }
#pragma unroll
    for (int i = 0; i < 2; ++i) {
        int c = tid + i * THREADS;
        int r = c >> 3, cc = c & 7;
        offB[i] = sw128((uint32_t)(r * 128 + cc * 16));
        pB1[i] = B1 + (size_t)(col0 + r) * DIM + cc * 8;
        pB3[i] = B3 + (size_t)(col0 + r) * DIM + cc * 8;
    }

    const int KT = DIM / BK;    // 64

    // prologue: stages 0..STAGES-2
#pragma unroll
    for (int s = 0; s < STAGES - 1; ++s) {
#pragma unroll
        for (int i = 0; i < 4; ++i) cp_async16(sA[s] + offA[i], pA[i] + s * BK);
#pragma unroll
        for (int i = 0; i < 2; ++i) cp_async16(sB1[s] + offB[i], pB1[i] + s * BK);
#pragma unroll
        for (int i = 0; i < 2; ++i) cp_async16(sB3[s] + offB[i], pB3[i] + s * BK);
        cp_async_commit();
    }
#pragma unroll
    for (int i = 0; i < 4; ++i) pA[i] += (STAGES - 1) * BK;
#pragma unroll
    for (int i = 0; i < 2; ++i) { pB1[i] += (STAGES - 1) * BK; pB3[i] += (STAGES - 1) * BK; }

    float acc1[4][2][4], acc3[4][2][4];
#pragma unroll
    for (int i = 0; i < 4; ++i)
#pragma unroll
        for (int j = 0; j < 2; ++j)
#pragma unroll
            for (int q = 0; q < 4; ++q) { acc1[i][j][q] = 0.f; acc3[i][j][q] = 0.f; }

    const int a_row = wm + ((lane >> 3) & 1) * 8 + (lane & 7);
    const int a_kb  = ((lane >> 4) & 1) * 16;
    const int b_row = wn + ((lane >> 4) & 1) * 8 + (lane & 7);
    const int b_kb  = ((lane >> 3) & 1) * 16;

    // swizzled ldsm offsets: addr(ks) = addr(0) ^ (ks*32)
    const uint32_t t_a = (uint32_t)(a_row & 7) << 4;
    const uint32_t t_b = (uint32_t)(b_row & 7) << 4;
    uint32_t asw[4];
#pragma unroll
    for (int im = 0; im < 4; ++im)
        asw[im] = (uint32_t)((a_row + im * 16) * 128) + ((uint32_t)a_kb ^ t_a);
    const uint32_t bsw = (uint32_t)(b_row * 128) + ((uint32_t)b_kb ^ t_b);

    for (int kt = 0; kt < KT; ++kt) {
        cp_async_wait<STAGES - 2>();   // stage kt%S ready
        __syncthreads();               // all warps done computing kt-1
        if (kt + STAGES - 1 < KT) {    // prefetch into just-freed stage
            const int sbuf = (kt + STAGES - 1) % STAGES;
#pragma unroll
            for (int i = 0; i < 4; ++i) cp_async16(sA[sbuf] + offA[i], pA[i]);
#pragma unroll
            for (int i = 0; i < 2; ++i) cp_async16(sB1[sbuf] + offB[i], pB1[i]);
#pragma unroll
            for (int i = 0; i < 2; ++i) cp_async16(sB3[sbuf] + offB[i], pB3[i]);
        }
        cp_async_commit();
#pragma unroll
        for (int i = 0; i < 4; ++i) pA[i] += BK;
#pragma unroll
        for (int i = 0; i < 2; ++i) { pB1[i] += BK; pB3[i] += BK; }

        const int st = kt % STAGES;
        uint32_t aoff[4];
#pragma unroll
        for (int im = 0; im < 4; ++im) aoff[im] = sA[st] + asw[im];
        const uint32_t b1off = sB1[st] + bsw;
        const uint32_t b3off = sB3[st] + bsw;

#pragma unroll
        for (int ks = 0; ks < 4; ++ks) {
            const uint32_t kx = (uint32_t)(ks * 32);
            uint32_t af[4][4], b1f[4], b3f[4];
            ldsm_x4(b1f, b1off ^ kx);
            ldsm_x4(b3f, b3off ^ kx);
#pragma unroll
            for (int im = 0; im < 4; ++im)
                ldsm_x4(af[im], aoff[im] ^ kx);
#pragma unroll
            for (int im = 0; im < 4; ++im) {
                mma16816(acc1[im][0], af[im], &b1f[0]);
                mma16816(acc1[im][1], af[im], &b1f[2]);
                mma16816(acc3[im][0], af[im], &b3f[0]);
                mma16816(acc3[im][1], af[im], &b3f[2]);
            }
        }
    }
    cp_async_wait<0>();

    // epilogue: h = silu(g1) * g3, fp16
    const int er = lane >> 2;
    const int ec = (lane & 3) * 2;
#pragma unroll
    for (int im = 0; im < 4; ++im) {
#pragma unroll
        for (int jn = 0; jn < 2; ++jn) {
            const float* c1 = acc1[im][jn];
            const float* c3 = acc3[im][jn];
            int gm = row0 + wm + im * 16 + er;
            int gn = col0 + wn + jn * 8 + ec;
            float h0 = (c1[0] / (1.f + __expf(-c1[0]))) * c3[0];
            float h1 = (c1[1] / (1.f + __expf(-c1[1]))) * c3[1];
            float h2 = (c1[2] / (1.f + __expf(-c1[2]))) * c3[2];
            float h3 = (c1[3] / (1.f + __expf(-c1[3]))) * c3[3];
            *reinterpret_cast<__half2*>(H + (size_t)gm * HID + gn) =
                __floats2half2_rn(h0, h1);
            *reinterpret_cast<__half2*>(H + (size_t)(gm + 8) * HID + gn) =
                __floats2half2_rn(h2, h3);
        }
    }
}

// ---------------------------------------------------------------------------
// GEMM2 (split-K=2): split 0 -> C, split 1 -> Cscr (plain stores, no atomics).
// CTA 128x128; 8 warps (2m x 4n), warp tile 64x32. 2 CTAs/SM.
// Raster: bm-fastest over ALL 32 m-tiles (H L2-resident; W2 streams once).
// ---------------------------------------------------------------------------
__global__ void __launch_bounds__(THREADS, 2)
gemm2_kernel(const __half* __restrict__ A, const __half* __restrict__ B,
             float* __restrict__ C, float* __restrict__ Cscr) {
    extern __shared__ __align__(1024) char smem[];
    const int tid = threadIdx.x;
    const int wid = tid >> 5, lane = tid & 31;
    const uint32_t sb = smem_u32(smem);

    const int TM = MTOK / G_BM;   // 32
    const int bid = blockIdx.x;
    const int bm = bid % TM;
    const int bn = bid / TM;
    const int row0 = bm * G_BM, col0 = bn * G_BN;

    const int KT_ALL = HID / BK;                 // 172
    const int KT_HALF = KT_ALL / G_SPLITK;       // 86
    const int kt0 = blockIdx.y * KT_HALF;
    const int kt1 = kt0 + KT_HALF;

    const int wm = (wid & 1) * 64;
    const int wn = (wid >> 1) * 32;

    uint32_t sA[STAGES], sB[STAGES];
#pragma unroll
    for (int s = 0; s < STAGES; ++s) {
        sA[s] = sb + s * G_STAGE;
        sB[s] = sA[s] + G_BM * 128;
    }

    // precomputed chunk descriptors: A 4 chunks, B 4 chunks per thread
    uint32_t offA[4], offB[4];
    const __half *pA[4], *pB[4];
#pragma unroll
    for (int i = 0; i < 4; ++i) {
        int c = tid + i * THREADS;
        int r = c >> 3, cc = c & 7;
        uint32_t o = sw128((uint32_t)(r * 128 + cc * 16));
        offA[i] = o; offB[i] = o;
        pA[i] = A + (size_t)(row0 + r) * HID + kt0 * BK + cc * 8;
        pB[i] = B + (size_t)(col0 + r) * HID + kt0 * BK + cc * 8;
    }

#pragma unroll
    for (int s = 0; s < STAGES - 1; ++s) {
#pragma unroll
        for (int i = 0; i < 4; ++i) cp_async16(sA[s] + offA[i], pA[i] + s * BK);
#pragma unroll
        for (int i = 0; i < 4; ++i) cp_async16(sB[s] + offB[i], pB[i] + s * BK);
        cp_async_commit();
    }
#pragma unroll
    for (int i = 0; i < 4; ++i) { pA[i] += (STAGES - 1) * BK; pB[i] += (STAGES - 1) * BK; }

    float acc[4][4][4];
#pragma unroll
    for (int i = 0; i < 4; ++i)
#pragma unroll
        for (int j = 0; j < 4; ++j)
#pragma unroll
            for (int q = 0; q < 4; ++q) acc[i][j][q] = 0.f;

    const int a_row = wm + ((lane >> 3) & 1) * 8 + (lane & 7);
    const int a_kb  = ((lane >> 4) & 1) * 16;
    const int b_row = wn + ((lane >> 4) & 1) * 8 + (lane & 7);
    const int b_kb  = ((lane >> 3) & 1) * 16;

    const uint32_t t_a = (uint32_t)(a_row & 7) << 4;
    const uint32_t t_b = (uint32_t)(b_row & 7) << 4;
    uint32_t asw[4];
#pragma unroll
    for (int im = 0; im < 4; ++im)
        asw[im] = (uint32_t)((a_row + im * 16) * 128) + ((uint32_t)a_kb ^ t_a);
    uint32_t bswr[2];
#pragma unroll
    for (int j16 = 0; j16 < 2; ++j16)
        bswr[j16] = (uint32_t)((b_row + j16 * 16) * 128) + ((uint32_t)b_kb ^ t_b);

    for (int kt = kt0; kt < kt1; ++kt) {
        cp_async_wait<STAGES - 2>();
        __syncthreads();
        if (kt + STAGES - 1 < kt1) {
            const int sbuf = (kt + STAGES - 1 - kt0) % STAGES;
#pragma unroll
            for (int i = 0; i < 4; ++i) cp_async16(sA[sbuf] + offA[i], pA[i]);
#pragma unroll
            for (int i = 0; i < 4; ++i) cp_async16(sB[sbuf] + offB[i], pB[i]);
        }
        cp_async_commit();
#pragma unroll
        for (int i = 0; i < 4; ++i) { pA[i] += BK; pB[i] += BK; }

        const int st = (kt - kt0) % STAGES;
        uint32_t aoff[4];
#pragma unroll
        for (int im = 0; im < 4; ++im) aoff[im] = sA[st] + asw[im];
        uint32_t boff[2];
#pragma unroll
        for (int j16 = 0; j16 < 2; ++j16) boff[j16] = sB[st] + bswr[j16];

#pragma unroll
        for (int ks = 0; ks < 4; ++ks) {
            const uint32_t kx = (uint32_t)(ks * 32);
            uint32_t af[4][4], bf[2][4];
#pragma unroll
            for (int j16 = 0; j16 < 2; ++j16)
                ldsm_x4(bf[j16], boff[j16] ^ kx);
#pragma unroll
            for (int im = 0; im < 4; ++im)
                ldsm_x4(af[im], aoff[im] ^ kx);
#pragma unroll
            for (int im = 0; im < 4; ++im)
#pragma unroll
                for (int j16 = 0; j16 < 2; ++j16) {
                    mma16816(acc[im][2 * j16],     af[im], &bf[j16][0]);
                    mma16816(acc[im][2 * j16 + 1], af[im], &bf[j16][2]);
                }
        }
    }
    cp_async_wait<0>();

    // epilogue: plain stores to this split's buffer
    float* D = (blockIdx.y == 0) ? C : Cscr;
    const int er = lane >> 2;
    const int ec = (lane & 3) * 2;
#pragma unroll
    for (int im = 0; im < 4; ++im) {
#pragma unroll
        for (int jn = 0; jn < 4; ++jn) {
            const float* c = acc[im][jn];
            int gm = row0 + wm + im * 16 + er;
            int gn = col0 + wn + jn * 8 + ec;
            *reinterpret_cast<float2*>(D + (size_t)gm * DIM + gn) =
                make_float2(c[0], c[1]);
            *reinterpret_cast<float2*>(D + (size_t)(gm + 8) * DIM + gn) =
                make_float2(c[2], c[3]);
        }
    }
}

// ---------------------------------------------------------------------------
// Host launcher. Two-phase side-stream structure (tail-filling only).
// ---------------------------------------------------------------------------
extern "C" void kernel_launch(void* const* d_in, const int* in_sizes, int n_in,
                              void* d_out, int out_size) {
    (void)in_sizes; (void)n_in;
    const float* x   = (const float*)d_in[0];
    const int*   w1c = (const int*)d_in[1];
    const float* w1a = (const float*)d_in[2];
    const int*   w2c = (const int*)d_in[3];
    const float* w2a = (const float*)d_in[4];
    const int*   w3c = (const int*)d_in[5];
    const float* w3a = (const float*)d_in[6];
    float* out = (float*)d_out;

    __half *pw1, *pw2, *pw3, *px, *ph;
    float* pscr;
    cudaGetSymbolAddress((void**)&pw1, g_w1);
    cudaGetSymbolAddress((void**)&pw2, g_w2);
    cudaGetSymbolAddress((void**)&pw3, g_w3);
    cudaGetSymbolAddress((void**)&px,  g_x);
    cudaGetSymbolAddress((void**)&ph,  g_h);
    cudaGetSymbolAddress((void**)&pscr, g_scr);

    cudaFuncSetAttribute(fused_gemm13_kernel,
                         cudaFuncAttributeMaxDynamicSharedMemorySize, F_SMEM);
    cudaFuncSetAttribute(gemm2_kernel,
                         cudaFuncAttributeMaxDynamicSharedMemorySize, G_SMEM);

    const int totalW = HID * DIM;          // 45,088,768
    const int wBlocks = totalW / 32 / 256; // 32 codes per thread, exact
    const int totalX = MTOK * DIM;

    cudaStream_t side;
    cudaStreamCreateWithFlags(&side, cudaStreamNonBlocking);
    cudaEvent_t evFork1, evJoin1, evFork2, evJoin2;
    cudaEventCreateWithFlags(&evFork1, cudaEventDisableTiming);
    cudaEventCreateWithFlags(&evJoin1, cudaEventDisableTiming);
    cudaEventCreateWithFlags(&evFork2, cudaEventDisableTiming);
    cudaEventCreateWithFlags(&evJoin2, cudaEventDisableTiming);

    // Phase 1: dq(W3) on side  ||  convert_x + dq(W1) on main
    cudaEventRecord(evFork1, 0);
    cudaStreamWaitEvent(side, evFork1, 0);
    dequant_nf4_kernel<DIM><<<wBlocks, 256, 0, side>>>(w3c, w3a, pw3, totalW);
    cudaEventRecord(evJoin1, side);

    convert_x_kernel<<<totalX / 8 / 256, 256>>>(x, px, totalX);
    dequant_nf4_kernel<DIM><<<wBlocks, 256>>>(w1c, w1a, pw1, totalW);
    cudaStreamWaitEvent(0, evJoin1, 0);

    // Phase 2 fork BEFORE the fused launch: dq(W2) fills the fused GEMM tail.
    cudaEventRecord(evFork2, 0);
    cudaStreamWaitEvent(side, evFork2, 0);
    dequant_nf4_kernel<HID><<<wBlocks, 256, 0, side>>>(w2c, w2a, pw2, totalW);
    cudaEventRecord(evJoin2, side);

    // H = silu(x W1^T) * (x W3^T)
    {
        const int TM = MTOK / F_BM;   // 32
        const int TN = HID / F_BN;    // 172
        fused_gemm13_kernel<<<TM * TN, THREADS, F_SMEM>>>(px, pw1, pw3, ph);
    }

    // Join, then out = H W2^T (split-K: split0 -> out, split1 -> scr)
    cudaStreamWaitEvent(0, evJoin2, 0);
    {
        const int TM = MTOK / G_BM;   // 32
        const int TN = DIM / G_BN;    // 32
        gemm2_kernel<<<dim3(TM * TN, G_SPLITK), THREADS, G_SMEM>>>(ph, pw2, out, pscr);
    }
    add_out_kernel<<<(out_size / 4 + 255) / 256, 256>>>(
        (float4*)out, (const float4*)pscr, out_size / 4);
}

// round 13
// speedup vs baseline: 1.0169x; 1.0169x over previous
#include <cuda_runtime.h>
#include <cuda_fp16.h>
#include <cstdint>
#include <cstddef>

// ---------------------------------------------------------------------------
// Problem constants
// ---------------------------------------------------------------------------
#define DIM   4096
#define HID   11008
#define MTOK  4096          // B*S = 2*2048

static constexpr int BK = 64;          // 64 fp16 = 128 bytes per row (SW128 atom)
static constexpr int THREADS = 256;    // 8 warps
static constexpr int STAGES = 3;

// Fused GEMM1+3: CTA 128(m) x 64(n per matrix); stage = A 16K + B1 8K + B3 8K
static constexpr int F_BM = 128;
static constexpr int F_BN = 64;                         // per weight matrix
static constexpr int F_STAGE = (F_BM + 2 * F_BN) * 128; // 32 KB
static constexpr int F_SMEM = STAGES * F_STAGE;         // 96 KB

// GEMM2: CTA 128 x 128, split-K = 2
static constexpr int G_BM = 128;
static constexpr int G_BN = 128;
static constexpr int G_SPLITK = 2;
static constexpr int G_STAGE = (G_BM + G_BN) * 128;     // 32 KB
static constexpr int G_SMEM = STAGES * G_STAGE;         // 96 KB

// ---------------------------------------------------------------------------
// NF4 codebook
// ---------------------------------------------------------------------------
__constant__ float c_nf4[16] = {
    -1.0f, -0.6961928009986877f, -0.5250730514526367f, -0.39491748809814453f,
    -0.28444138169288635f, -0.18477343022823334f, -0.09105003625154495f, 0.0f,
    0.07958029955625534f, 0.16093020141124725f, 0.24611230194568634f,
    0.33791524171829224f, 0.44070982933044434f, 0.5626170039176941f,
    0.6989939212799072f, 1.0f};

// ---------------------------------------------------------------------------
// Static device scratch
// ---------------------------------------------------------------------------
__device__ __align__(256) __half g_w1[(size_t)HID * DIM];
__device__ __align__(256) __half g_w3[(size_t)HID * DIM];
__device__ __align__(256) __half g_w2[(size_t)DIM * HID];
__device__ __align__(256) __half g_x [(size_t)MTOK * DIM];
__device__ __align__(256) __half g_h [(size_t)MTOK * HID];

// ---------------------------------------------------------------------------
// PTX helpers (sm_100 baseline: cp.async, ldmatrix, mma.sync)
// ---------------------------------------------------------------------------
__device__ __forceinline__ uint32_t smem_u32(const void* p) {
    uint32_t r;
    asm("{ .reg .u64 t; cvta.to.shared.u64 t, %1; cvt.u32.u64 %0, t; }"
        : "=r"(r) : "l"(p));
    return r;
}

__device__ __forceinline__ void cp_async16(uint32_t dst, const void* src) {
    asm volatile("cp.async.cg.shared.global [%0], [%1], 16;" :: "r"(dst), "l"(src));
}
__device__ __forceinline__ void cp_async_commit() {
    asm volatile("cp.async.commit_group;" ::: "memory");
}
template <int N>
__device__ __forceinline__ void cp_async_wait() {
    asm volatile("cp.async.wait_group %0;" :: "n"(N) : "memory");
}

__device__ __forceinline__ void ldsm_x4(uint32_t* r, uint32_t addr) {
    asm volatile("ldmatrix.sync.aligned.m8n8.x4.shared.b16 {%0,%1,%2,%3}, [%4];"
                 : "=r"(r[0]), "=r"(r[1]), "=r"(r[2]), "=r"(r[3]) : "r"(addr));
}

__device__ __forceinline__ void mma16816(float* c, const uint32_t* a, const uint32_t* b) {
    asm volatile(
        "mma.sync.aligned.m16n8k16.row.col.f32.f16.f16.f32 "
        "{%0,%1,%2,%3}, {%4,%5,%6,%7}, {%8,%9}, {%0,%1,%2,%3};"
        : "+f"(c[0]), "+f"(c[1]), "+f"(c[2]), "+f"(c[3])
        : "r"(a[0]), "r"(a[1]), "r"(a[2]), "r"(a[3]), "r"(b[0]), "r"(b[1]));
}

__device__ __forceinline__ uint32_t sw128(uint32_t off) {
    return off ^ ((off >> 3) & 0x70);
}

// ---------------------------------------------------------------------------
// Dequant (shfl-LUT, 32 elems/thread) / convert / zero kernels
// ---------------------------------------------------------------------------
template <int K>
__global__ void __launch_bounds__(256)
dequant_nf4_kernel(const int* __restrict__ codes, const float* __restrict__ absmax,
                   __half* __restrict__ out, int total) {
    const int t = blockIdx.x * 256 + threadIdx.x;
    const int base = t * 32;                 // 32 codes per thread
    if (base >= total) return;

    // Register LUT: lane i holds nf4[i & 15]; lookup via one shfl.
    const float tbl = c_nf4[threadIdx.x & 15];

    // 32 elems stay inside one 64-wide absmax block (base is 32-aligned).
    const int row = base / K;                // K is a compile-time constant
    const int col = base - row * K;
    const float am = absmax[row * (K >> 6) + (col >> 6)];

    int4 c[8];
#pragma unroll
    for (int i = 0; i < 8; ++i)
        c[i] = reinterpret_cast<const int4*>(codes + base)[i];

    __half2 hs[16];
#pragma unroll
    for (int i = 0; i < 8; ++i) {
        float v0 = __shfl_sync(0xffffffffu, tbl, c[i].x & 15);
        float v1 = __shfl_sync(0xffffffffu, tbl, c[i].y & 15);
        float v2 = __shfl_sync(0xffffffffu, tbl, c[i].z & 15);
        float v3 = __shfl_sync(0xffffffffu, tbl, c[i].w & 15);
        hs[2 * i]     = __floats2half2_rn(v0 * am, v1 * am);
        hs[2 * i + 1] = __floats2half2_rn(v2 * am, v3 * am);
    }
#pragma unroll
    for (int i = 0; i < 4; ++i)
        reinterpret_cast<uint4*>(out + base)[i] =
            reinterpret_cast<const uint4*>(hs)[i];
}

__global__ void __launch_bounds__(256)
convert_x_kernel(const float* __restrict__ x, __half* __restrict__ out, int total) {
    int t = blockIdx.x * 256 + threadIdx.x;
    int base = t * 8;
    if (base >= total) return;
    float4 a = reinterpret_cast<const float4*>(x + base)[0];
    float4 b = reinterpret_cast<const float4*>(x + base)[1];
    __half2 hs[4];
    hs[0] = __floats2half2_rn(a.x, a.y);
    hs[1] = __floats2half2_rn(a.z, a.w);
    hs[2] = __floats2half2_rn(b.x, b.y);
    hs[3] = __floats2half2_rn(b.z, b.w);
    *reinterpret_cast<uint4*>(out + base) = *reinterpret_cast<const uint4*>(hs);
}

__global__ void __launch_bounds__(256)
zero_out_kernel(float4* __restrict__ p, int total4) {
    int t = blockIdx.x * 256 + threadIdx.x;
    if (t < total4) p[t] = make_float4(0.f, 0.f, 0.f, 0.f);
}

// ---------------------------------------------------------------------------
// Fused GEMM1+GEMM3+SwiGLU:  H = silu(x W1^T) * (x W3^T), fp16 out.
// CTA 128m x 64n per matrix; 8 warps (2m x 4n), warp tile 64m x 16n/matrix.
// 3-stage cp.async pipeline, one __syncthreads per k-tile, 2 CTAs/SM.
// Grouped raster G=16 (measured optimum).
// ---------------------------------------------------------------------------
__global__ void __launch_bounds__(THREADS, 2)
fused_gemm13_kernel(const __half* __restrict__ A, const __half* __restrict__ B1,
                    const __half* __restrict__ B3, __half* __restrict__ H) {
    extern __shared__ __align__(1024) char smem[];
    const int tid = threadIdx.x;
    const int wid = tid >> 5, lane = tid & 31;
    const uint32_t sb = smem_u32(smem);

    // grouped raster: groups of G m-tiles sweep all n-tiles
    const int TN = HID / F_BN;   // 172
    const int G = 16;
    const int bid = blockIdx.x;
    const int group = bid / (G * TN);
    const int rem = bid - group * (G * TN);
    const int bm = group * G + (rem % G);
    const int bn = rem / G;
    const int row0 = bm * F_BM, col0 = bn * F_BN;

    const int wm = (wid & 1) * 64;       // warp m offset
    const int wn = (wid >> 1) * 16;      // warp n offset (per weight matrix)

    uint32_t sA[STAGES], sB1[STAGES], sB3[STAGES];
#pragma unroll
    for (int s = 0; s < STAGES; ++s) {
        sA[s]  = sb + s * F_STAGE;
        sB1[s] = sA[s] + F_BM * 128;
        sB3[s] = sB1[s] + F_BN * 128;
    }

    // ---- precomputed cp.async chunk descriptors (loop-invariant) ----
    uint32_t offA[4], offB[2];
    const __half *pA[4], *pB1[2], *pB3[2];
#pragma unroll
    for (int i = 0; i < 4; ++i) {
        int c = tid + i * THREADS;
        int r = c >> 3, cc = c & 7;
        offA[i] = sw128((uint32_t)(r * 128 + cc * 16));
        pA[i] = A + (size_t)(row0 + r) * DIM + cc * 8;
    }
#pragma unroll
    for (int i = 0; i < 2; ++i) {
        int c = tid + i * THREADS;
        int r = c >> 3, cc = c & 7;
        offB[i] = sw128((uint32_t)(r * 128 + cc * 16));
        pB1[i] = B1 + (size_t)(col0 + r) * DIM + cc * 8;
        pB3[i] = B3 + (size_t)(col0 + r) * DIM + cc * 8;
    }

    const int KT = DIM / BK;    // 64

    // prologue: stages 0..STAGES-2
#pragma unroll
    for (int s = 0; s < STAGES - 1; ++s) {
#pragma unroll
        for (int i = 0; i < 4; ++i) cp_async16(sA[s] + offA[i], pA[i] + s * BK);
#pragma unroll
        for (int i = 0; i < 2; ++i) cp_async16(sB1[s] + offB[i], pB1[i] + s * BK);
#pragma unroll
        for (int i = 0; i < 2; ++i) cp_async16(sB3[s] + offB[i], pB3[i] + s * BK);
        cp_async_commit();
    }
#pragma unroll
    for (int i = 0; i < 4; ++i) pA[i] += (STAGES - 1) * BK;
#pragma unroll
    for (int i = 0; i < 2; ++i) { pB1[i] += (STAGES - 1) * BK; pB3[i] += (STAGES - 1) * BK; }

    float acc1[4][2][4], acc3[4][2][4];
#pragma unroll
    for (int i = 0; i < 4; ++i)
#pragma unroll
        for (int j = 0; j < 2; ++j)
#pragma unroll
            for (int q = 0; q < 4; ++q) { acc1[i][j][q] = 0.f; acc3[i][j][q] = 0.f; }

    const int a_row = wm + ((lane >> 3) & 1) * 8 + (lane & 7);
    const int a_kb  = ((lane >> 4) & 1) * 16;
    const int b_row = wn + ((lane >> 4) & 1) * 8 + (lane & 7);
    const int b_kb  = ((lane >> 3) & 1) * 16;

    // swizzled ldsm offsets: addr(ks) = addr(0) ^ (ks*32)
    const uint32_t t_a = (uint32_t)(a_row & 7) << 4;
    const uint32_t t_b = (uint32_t)(b_row & 7) << 4;
    uint32_t asw[4];
#pragma unroll
    for (int im = 0; im < 4; ++im)
        asw[im] = (uint32_t)((a_row + im * 16) * 128) + ((uint32_t)a_kb ^ t_a);
    const uint32_t bsw = (uint32_t)(b_row * 128) + ((uint32_t)b_kb ^ t_b);

    for (int kt = 0; kt < KT; ++kt) {
        cp_async_wait<STAGES - 2>();   // stage kt%S ready
        __syncthreads();               // all warps done computing kt-1
        if (kt + STAGES - 1 < KT) {    // prefetch into just-freed stage
            const int sbuf = (kt + STAGES - 1) % STAGES;
#pragma unroll
            for (int i = 0; i < 4; ++i) cp_async16(sA[sbuf] + offA[i], pA[i]);
#pragma unroll
            for (int i = 0; i < 2; ++i) cp_async16(sB1[sbuf] + offB[i], pB1[i]);
#pragma unroll
            for (int i = 0; i < 2; ++i) cp_async16(sB3[sbuf] + offB[i], pB3[i]);
        }
        cp_async_commit();
#pragma unroll
        for (int i = 0; i < 4; ++i) pA[i] += BK;
#pragma unroll
        for (int i = 0; i < 2; ++i) { pB1[i] += BK; pB3[i] += BK; }

        const int st = kt % STAGES;
        uint32_t aoff[4];
#pragma unroll
        for (int im = 0; im < 4; ++im) aoff[im] = sA[st] + asw[im];
        const uint32_t b1off = sB1[st] + bsw;
        const uint32_t b3off = sB3[st] + bsw;

#pragma unroll
        for (int ks = 0; ks < 4; ++ks) {
            const uint32_t kx = (uint32_t)(ks * 32);
            uint32_t af[4][4], b1f[4], b3f[4];
            ldsm_x4(b1f, b1off ^ kx);
            ldsm_x4(b3f, b3off ^ kx);
#pragma unroll
            for (int im = 0; im < 4; ++im)
                ldsm_x4(af[im], aoff[im] ^ kx);
#pragma unroll
            for (int im = 0; im < 4; ++im) {
                mma16816(acc1[im][0], af[im], &b1f[0]);
                mma16816(acc1[im][1], af[im], &b1f[2]);
                mma16816(acc3[im][0], af[im], &b3f[0]);
                mma16816(acc3[im][1], af[im], &b3f[2]);
            }
        }
    }
    cp_async_wait<0>();

    // epilogue: h = silu(g1) * g3, fp16
    const int er = lane >> 2;
    const int ec = (lane & 3) * 2;
#pragma unroll
    for (int im = 0; im < 4; ++im) {
#pragma unroll
        for (int jn = 0; jn < 2; ++jn) {
            const float* c1 = acc1[im][jn];
            const float* c3 = acc3[im][jn];
            int gm = row0 + wm + im * 16 + er;
            int gn = col0 + wn + jn * 8 + ec;
            float h0 = (c1[0] / (1.f + __expf(-c1[0]))) * c3[0];
            float h1 = (c1[1] / (1.f + __expf(-c1[1]))) * c3[1];
            float h2 = (c1[2] / (1.f + __expf(-c1[2]))) * c3[2];
            float h3 = (c1[3] / (1.f + __expf(-c1[3]))) * c3[3];
            *reinterpret_cast<__half2*>(H + (size_t)gm * HID + gn) =
                __floats2half2_rn(h0, h1);
            *reinterpret_cast<__half2*>(H + (size_t)(gm + 8) * HID + gn) =
                __floats2half2_rn(h2, h3);
        }
    }
}

// ---------------------------------------------------------------------------
// GEMM2 (split-K=2): both splits red.global.add into C (zeroed beforehand).
// CTA 128x128; 8 warps (2m x 4n), warp tile 64x32. 2 CTAs/SM. Grouped G=16.
// ---------------------------------------------------------------------------
__global__ void __launch_bounds__(THREADS, 2)
gemm2_kernel(const __half* __restrict__ A, const __half* __restrict__ B,
             float* __restrict__ C) {
    extern __shared__ __align__(1024) char smem[];
    const int tid = threadIdx.x;
    const int wid = tid >> 5, lane = tid & 31;
    const uint32_t sb = smem_u32(smem);

    const int TN = DIM / G_BN;    // 32
    const int G = 16;
    const int bid = blockIdx.x;
    const int group = bid / (G * TN);
    const int rem = bid - group * (G * TN);
    const int bm = group * G + (rem % G);
    const int bn = rem / G;
    const int row0 = bm * G_BM, col0 = bn * G_BN;

    const int KT_ALL = HID / BK;                 // 172
    const int KT_HALF = KT_ALL / G_SPLITK;       // 86
    const int kt0 = blockIdx.y * KT_HALF;
    const int kt1 = kt0 + KT_HALF;

    const int wm = (wid & 1) * 64;
    const int wn = (wid >> 1) * 32;

    uint32_t sA[STAGES], sB[STAGES];
#pragma unroll
    for (int s = 0; s < STAGES; ++s) {
        sA[s] = sb + s * G_STAGE;
        sB[s] = sA[s] + G_BM * 128;
    }

    // precomputed chunk descriptors: A 4 chunks, B 4 chunks per thread
    uint32_t offA[4], offB[4];
    const __half *pA[4], *pB[4];
#pragma unroll
    for (int i = 0; i < 4; ++i) {
        int c = tid + i * THREADS;
        int r = c >> 3, cc = c & 7;
        uint32_t o = sw128((uint32_t)(r * 128 + cc * 16));
        offA[i] = o; offB[i] = o;
        pA[i] = A + (size_t)(row0 + r) * HID + kt0 * BK + cc * 8;
        pB[i] = B + (size_t)(col0 + r) * HID + kt0 * BK + cc * 8;
    }

#pragma unroll
    for (int s = 0; s < STAGES - 1; ++s) {
#pragma unroll
        for (int i = 0; i < 4; ++i) cp_async16(sA[s] + offA[i], pA[i] + s * BK);
#pragma unroll
        for (int i = 0; i < 4; ++i) cp_async16(sB[s] + offB[i], pB[i] + s * BK);
        cp_async_commit();
    }
#pragma unroll
    for (int i = 0; i < 4; ++i) { pA[i] += (STAGES - 1) * BK; pB[i] += (STAGES - 1) * BK; }

    float acc[4][4][4];
#pragma unroll
    for (int i = 0; i < 4; ++i)
#pragma unroll
        for (int j = 0; j < 4; ++j)
#pragma unroll
            for (int q = 0; q < 4; ++q) acc[i][j][q] = 0.f;

    const int a_row = wm + ((lane >> 3) & 1) * 8 + (lane & 7);
    const int a_kb  = ((lane >> 4) & 1) * 16;
    const int b_row = wn + ((lane >> 4) & 1) * 8 + (lane & 7);
    const int b_kb  = ((lane >> 3) & 1) * 16;

    const uint32_t t_a = (uint32_t)(a_row & 7) << 4;
    const uint32_t t_b = (uint32_t)(b_row & 7) << 4;
    uint32_t asw[4];
#pragma unroll
    for (int im = 0; im < 4; ++im)
        asw[im] = (uint32_t)((a_row + im * 16) * 128) + ((uint32_t)a_kb ^ t_a);
    uint32_t bswr[2];
#pragma unroll
    for (int j16 = 0; j16 < 2; ++j16)
        bswr[j16] = (uint32_t)((b_row + j16 * 16) * 128) + ((uint32_t)b_kb ^ t_b);

    for (int kt = kt0; kt < kt1; ++kt) {
        cp_async_wait<STAGES - 2>();
        __syncthreads();
        if (kt + STAGES - 1 < kt1) {
            const int sbuf = (kt + STAGES - 1 - kt0) % STAGES;
#pragma unroll
            for (int i = 0; i < 4; ++i) cp_async16(sA[sbuf] + offA[i], pA[i]);
#pragma unroll
            for (int i = 0; i < 4; ++i) cp_async16(sB[sbuf] + offB[i], pB[i]);
        }
        cp_async_commit();
#pragma unroll
        for (int i = 0; i < 4; ++i) { pA[i] += BK; pB[i] += BK; }

        const int st = (kt - kt0) % STAGES;
        uint32_t aoff[4];
#pragma unroll
        for (int im = 0; im < 4; ++im) aoff[im] = sA[st] + asw[im];
        uint32_t boff[2];
#pragma unroll
        for (int j16 = 0; j16 < 2; ++j16) boff[j16] = sB[st] + bswr[j16];

#pragma unroll
        for (int ks = 0; ks < 4; ++ks) {
            const uint32_t kx = (uint32_t)(ks * 32);
            uint32_t af[4][4], bf[2][4];
#pragma unroll
            for (int j16 = 0; j16 < 2; ++j16)
                ldsm_x4(bf[j16], boff[j16] ^ kx);
#pragma unroll
            for (int im = 0; im < 4; ++im)
                ldsm_x4(af[im], aoff[im] ^ kx);
#pragma unroll
            for (int im = 0; im < 4; ++im)
#pragma unroll
                for (int j16 = 0; j16 < 2; ++j16) {
                    mma16816(acc[im][2 * j16],     af[im], &bf[j16][0]);
                    mma16816(acc[im][2 * j16 + 1], af[im], &bf[j16][2]);
                }
        }
    }
    cp_async_wait<0>();

    // epilogue: red.global accumulate (atomicAdd with unused result -> RED)
    const int er = lane >> 2;
    const int ec = (lane & 3) * 2;
#pragma unroll
    for (int im = 0; im < 4; ++im) {
#pragma unroll
        for (int jn = 0; jn < 4; ++jn) {
            const float* c = acc[im][jn];
            int gm = row0 + wm + im * 16 + er;
            int gn = col0 + wn + jn * 8 + ec;
            atomicAdd(C + (size_t)gm * DIM + gn,     c[0]);
            atomicAdd(C + (size_t)gm * DIM + gn + 1, c[1]);
            atomicAdd(C + (size_t)(gm + 8) * DIM + gn,     c[2]);
            atomicAdd(C + (size_t)(gm + 8) * DIM + gn + 1, c[3]);
        }
    }
}

// ---------------------------------------------------------------------------
// Host launcher. Two-phase side-stream overlap; zero_out hidden under fused.
// ---------------------------------------------------------------------------
extern "C" void kernel_launch(void* const* d_in, const int* in_sizes, int n_in,
                              void* d_out, int out_size) {
    (void)in_sizes; (void)n_in;
    const float* x   = (const float*)d_in[0];
    const int*   w1c = (const int*)d_in[1];
    const float* w1a = (const float*)d_in[2];
    const int*   w2c = (const int*)d_in[3];
    const float* w2a = (const float*)d_in[4];
    const int*   w3c = (const int*)d_in[5];
    const float* w3a = (const float*)d_in[6];
    float* out = (float*)d_out;

    __half *pw1, *pw2, *pw3, *px, *ph;
    cudaGetSymbolAddress((void**)&pw1, g_w1);
    cudaGetSymbolAddress((void**)&pw2, g_w2);
    cudaGetSymbolAddress((void**)&pw3, g_w3);
    cudaGetSymbolAddress((void**)&px,  g_x);
    cudaGetSymbolAddress((void**)&ph,  g_h);

    cudaFuncSetAttribute(fused_gemm13_kernel,
                         cudaFuncAttributeMaxDynamicSharedMemorySize, F_SMEM);
    cudaFuncSetAttribute(gemm2_kernel,
                         cudaFuncAttributeMaxDynamicSharedMemorySize, G_SMEM);

    const int totalW = HID * DIM;          // 45,088,768
    const int wBlocks = totalW / 32 / 256; // 32 codes per thread, exact
    const int totalX = MTOK * DIM;

    cudaStream_t side;
    cudaStreamCreateWithFlags(&side, cudaStreamNonBlocking);
    cudaEvent_t evFork1, evJoin1, evFork2, evJoin2;
    cudaEventCreateWithFlags(&evFork1, cudaEventDisableTiming);
    cudaEventCreateWithFlags(&evJoin1, cudaEventDisableTiming);
    cudaEventCreateWithFlags(&evFork2, cudaEventDisableTiming);
    cudaEventCreateWithFlags(&evJoin2, cudaEventDisableTiming);

    // Phase 1: dq(W3) on side  ||  convert_x + dq(W1) on main
    cudaEventRecord(evFork1, 0);
    cudaStreamWaitEvent(side, evFork1, 0);
    dequant_nf4_kernel<DIM><<<wBlocks, 256, 0, side>>>(w3c, w3a, pw3, totalW);
    cudaEventRecord(evJoin1, side);

    convert_x_kernel<<<totalX / 8 / 256, 256>>>(x, px, totalX);
    dequant_nf4_kernel<DIM><<<wBlocks, 256>>>(w1c, w1a, pw1, totalW);
    cudaStreamWaitEvent(0, evJoin1, 0);

    // Phase 2 fork BEFORE the fused launch: dq(W2) + zero(out) overlap the GEMM.
    cudaEventRecord(evFork2, 0);
    cudaStreamWaitEvent(side, evFork2, 0);
    dequant_nf4_kernel<HID><<<wBlocks, 256, 0, side>>>(w2c, w2a, pw2, totalW);
    zero_out_kernel<<<(out_size / 4 + 255) / 256, 256, 0, side>>>(
        (float4*)out, out_size / 4);
    cudaEventRecord(evJoin2, side);

    // H = silu(x W1^T) * (x W3^T)
    {
        const int TM = MTOK / F_BM;   // 32
        const int TN = HID / F_BN;    // 172
        fused_gemm13_kernel<<<TM * TN, THREADS, F_SMEM>>>(px, pw1, pw3, ph);
    }

    // Join, then out += H W2^T (split-K via RED)
    cudaStreamWaitEvent(0, evJoin2, 0);
    {
        const int TM = MTOK / G_BM;   // 32
        const int TN = DIM / G_BN;    // 32
        gemm2_kernel<<<dim3(TM * TN, G_SPLITK), THREADS, G_SMEM>>>(ph, pw2, out);
    }
}

// round 14
// speedup vs baseline: 1.0199x; 1.0029x over previous
#include <cuda_runtime.h>
#include <cuda_fp16.h>
#include <cstdint>
#include <cstddef>

// ---------------------------------------------------------------------------
// Problem constants
// ---------------------------------------------------------------------------
#define DIM   4096
#define HID   11008
#define MTOK  4096          // B*S = 2*2048

static constexpr int BK = 64;          // 64 fp16 = 128 bytes per row (SW128 atom)
static constexpr int THREADS = 256;    // 8 warps
static constexpr int STAGES = 3;

// Fused GEMM1+3: CTA 128(m) x 64(n per matrix); stage = A 16K + B1 8K + B3 8K
static constexpr int F_BM = 128;
static constexpr int F_BN = 64;                         // per weight matrix
static constexpr int F_STAGE = (F_BM + 2 * F_BN) * 128; // 32 KB
static constexpr int F_SMEM = STAGES * F_STAGE;         // 96 KB

// GEMM2: CTA 128 x 128, split-K = 2
static constexpr int G_BM = 128;
static constexpr int G_BN = 128;
static constexpr int G_SPLITK = 2;
static constexpr int G_STAGE = (G_BM + G_BN) * 128;     // 32 KB
static constexpr int G_SMEM = STAGES * G_STAGE;         // 96 KB

// ---------------------------------------------------------------------------
// NF4 codebook
// ---------------------------------------------------------------------------
__constant__ float c_nf4[16] = {
    -1.0f, -0.6961928009986877f, -0.5250730514526367f, -0.39491748809814453f,
    -0.28444138169288635f, -0.18477343022823334f, -0.09105003625154495f, 0.0f,
    0.07958029955625534f, 0.16093020141124725f, 0.24611230194568634f,
    0.33791524171829224f, 0.44070982933044434f, 0.5626170039176941f,
    0.6989939212799072f, 1.0f};

// ---------------------------------------------------------------------------
// Static device scratch
// ---------------------------------------------------------------------------
__device__ __align__(256) __half g_w1[(size_t)HID * DIM];
__device__ __align__(256) __half g_w3[(size_t)HID * DIM];
__device__ __align__(256) __half g_w2[(size_t)DIM * HID];
__device__ __align__(256) __half g_x [(size_t)MTOK * DIM];
__device__ __align__(256) __half g_h [(size_t)MTOK * HID];

// ---------------------------------------------------------------------------
// PTX helpers (sm_100 baseline: cp.async, ldmatrix, mma.sync)
// ---------------------------------------------------------------------------
__device__ __forceinline__ uint32_t smem_u32(const void* p) {
    uint32_t r;
    asm("{ .reg .u64 t; cvta.to.shared.u64 t, %1; cvt.u32.u64 %0, t; }"
        : "=r"(r) : "l"(p));
    return r;
}

__device__ __forceinline__ void cp_async16(uint32_t dst, const void* src) {
    asm volatile("cp.async.cg.shared.global [%0], [%1], 16;" :: "r"(dst), "l"(src));
}
__device__ __forceinline__ void cp_async_commit() {
    asm volatile("cp.async.commit_group;" ::: "memory");
}
template <int N>
__device__ __forceinline__ void cp_async_wait() {
    asm volatile("cp.async.wait_group %0;" :: "n"(N) : "memory");
}

__device__ __forceinline__ void ldsm_x4(uint32_t* r, uint32_t addr) {
    asm volatile("ldmatrix.sync.aligned.m8n8.x4.shared.b16 {%0,%1,%2,%3}, [%4];"
                 : "=r"(r[0]), "=r"(r[1]), "=r"(r[2]), "=r"(r[3]) : "r"(addr));
}

__device__ __forceinline__ void mma16816(float* c, const uint32_t* a, const uint32_t* b) {
    asm volatile(
        "mma.sync.aligned.m16n8k16.row.col.f32.f16.f16.f32 "
        "{%0,%1,%2,%3}, {%4,%5,%6,%7}, {%8,%9}, {%0,%1,%2,%3};"
        : "+f"(c[0]), "+f"(c[1]), "+f"(c[2]), "+f"(c[3])
        : "r"(a[0]), "r"(a[1]), "r"(a[2]), "r"(a[3]), "r"(b[0]), "r"(b[1]));
}

__device__ __forceinline__ uint32_t sw128(uint32_t off) {
    return off ^ ((off >> 3) & 0x70);
}

// ---------------------------------------------------------------------------
// Dequant (ALU PRMT decode, 32 elems/thread) / convert / zero kernels
// ---------------------------------------------------------------------------
// Select fp16 bits of nf4[idx] from 8 packed registers: SEL window + PRMT.
__device__ __forceinline__ float nf4_val(uint32_t idx,
    uint32_t h0, uint32_t h1, uint32_t h2, uint32_t h3,
    uint32_t h4, uint32_t h5, uint32_t h6, uint32_t h7) {
    uint32_t a = (idx & 8) ? ((idx & 4) ? h6 : h4) : ((idx & 4) ? h2 : h0);
    uint32_t b = (idx & 8) ? ((idx & 4) ? h7 : h5) : ((idx & 4) ? h3 : h1);
    uint32_t sel = (idx & 3) * 0x22u + 0x10u;     // bytes (2j, 2j+1)
    uint32_t w = __byte_perm(a, b, sel);
    return __half2float(__ushort_as_half((unsigned short)(w & 0xffffu)));
}

template <int K>
__global__ void __launch_bounds__(256)
dequant_nf4_kernel(const int* __restrict__ codes, const float* __restrict__ absmax,
                   __half* __restrict__ out, int total) {
    const int t = blockIdx.x * 256 + threadIdx.x;
    const int base = t * 32;                 // 32 codes per thread
    if (base >= total) return;

    // Packed fp16 table (uniform constant reads; no divergent c-bank access).
    uint32_t h[8];
#pragma unroll
    for (int i = 0; i < 8; ++i) {
        __half2 p = __floats2half2_rn(c_nf4[2 * i], c_nf4[2 * i + 1]);
        h[i] = *reinterpret_cast<uint32_t*>(&p);
    }

    // 32 elems stay inside one 64-wide absmax block (base is 32-aligned).
    const int row = base / K;                // K is a compile-time constant
    const int col = base - row * K;
    const float am = absmax[row * (K >> 6) + (col >> 6)];

    int4 c[8];
#pragma unroll
    for (int i = 0; i < 8; ++i)
        c[i] = reinterpret_cast<const int4*>(codes + base)[i];

    __half2 hs[16];
#pragma unroll
    for (int i = 0; i < 8; ++i) {
        float v0 = nf4_val((uint32_t)c[i].x & 15u, h[0], h[1], h[2], h[3], h[4], h[5], h[6], h[7]);
        float v1 = nf4_val((uint32_t)c[i].y & 15u, h[0], h[1], h[2], h[3], h[4], h[5], h[6], h[7]);
        float v2 = nf4_val((uint32_t)c[i].z & 15u, h[0], h[1], h[2], h[3], h[4], h[5], h[6], h[7]);
        float v3 = nf4_val((uint32_t)c[i].w & 15u, h[0], h[1], h[2], h[3], h[4], h[5], h[6], h[7]);
        hs[2 * i]     = __floats2half2_rn(v0 * am, v1 * am);
        hs[2 * i + 1] = __floats2half2_rn(v2 * am, v3 * am);
    }
#pragma unroll
    for (int i = 0; i < 4; ++i)
        reinterpret_cast<uint4*>(out + base)[i] =
            reinterpret_cast<const uint4*>(hs)[i];
}

__global__ void __launch_bounds__(256)
convert_x_kernel(const float* __restrict__ x, __half* __restrict__ out, int total) {
    int t = blockIdx.x * 256 + threadIdx.x;
    int base = t * 8;
    if (base >= total) return;
    float4 a = reinterpret_cast<const float4*>(x + base)[0];
    float4 b = reinterpret_cast<const float4*>(x + base)[1];
    __half2 hs[4];
    hs[0] = __floats2half2_rn(a.x, a.y);
    hs[1] = __floats2half2_rn(a.z, a.w);
    hs[2] = __floats2half2_rn(b.x, b.y);
    hs[3] = __floats2half2_rn(b.z, b.w);
    *reinterpret_cast<uint4*>(out + base) = *reinterpret_cast<const uint4*>(hs);
}

__global__ void __launch_bounds__(256)
zero_out_kernel(float4* __restrict__ p, int total4) {
    int t = blockIdx.x * 256 + threadIdx.x;
    if (t < total4) p[t] = make_float4(0.f, 0.f, 0.f, 0.f);
}

// ---------------------------------------------------------------------------
// Fused GEMM1+GEMM3+SwiGLU:  H = silu(x W1^T) * (x W3^T), fp16 out.
// CTA 128m x 64n per matrix; 8 warps (2m x 4n), warp tile 64m x 16n/matrix.
// 3-stage cp.async pipeline, one __syncthreads per k-tile, 2 CTAs/SM.
// Grouped raster G=16 (measured optimum).
// ---------------------------------------------------------------------------
__global__ void __launch_bounds__(THREADS, 2)
fused_gemm13_kernel(const __half* __restrict__ A, const __half* __restrict__ B1,
                    const __half* __restrict__ B3, __half* __restrict__ H) {
    extern __shared__ __align__(1024) char smem[];
    const int tid = threadIdx.x;
    const int wid = tid >> 5, lane = tid & 31;
    const uint32_t sb = smem_u32(smem);

    // grouped raster: groups of G m-tiles sweep all n-tiles
    const int TN = HID / F_BN;   // 172
    const int G = 16;
    const int bid = blockIdx.x;
    const int group = bid / (G * TN);
    const int rem = bid - group * (G * TN);
    const int bm = group * G + (rem % G);
    const int bn = rem / G;
    const int row0 = bm * F_BM, col0 = bn * F_BN;

    const int wm = (wid & 1) * 64;       // warp m offset
    const int wn = (wid >> 1) * 16;      // warp n offset (per weight matrix)

    uint32_t sA[STAGES], sB1[STAGES], sB3[STAGES];
#pragma unroll
    for (int s = 0; s < STAGES; ++s) {
        sA[s]  = sb + s * F_STAGE;
        sB1[s] = sA[s] + F_BM * 128;
        sB3[s] = sB1[s] + F_BN * 128;
    }

    // ---- precomputed cp.async chunk descriptors (loop-invariant) ----
    uint32_t offA[4], offB[2];
    const __half *pA[4], *pB1[2], *pB3[2];
#pragma unroll
    for (int i = 0; i < 4; ++i) {
        int c = tid + i * THREADS;
        int r = c >> 3, cc = c & 7;
        offA[i] = sw128((uint32_t)(r * 128 + cc * 16));
        pA[i] = A + (size_t)(row0 + r) * DIM + cc * 8;
    }
#pragma unroll
    for (int i = 0; i < 2; ++i) {
        int c = tid + i * THREADS;
        int r = c >> 3, cc = c & 7;
        offB[i] = sw128((uint32_t)(r * 128 + cc * 16));
        pB1[i] = B1 + (size_t)(col0 + r) * DIM + cc * 8;
        pB3[i] = B3 + (size_t)(col0 + r) * DIM + cc * 8;
    }

    const int KT = DIM / BK;    // 64

    // prologue: stages 0..STAGES-2
#pragma unroll
    for (int s = 0; s < STAGES - 1; ++s) {
#pragma unroll
        for (int i = 0; i < 4; ++i) cp_async16(sA[s] + offA[i], pA[i] + s * BK);
#pragma unroll
        for (int i = 0; i < 2; ++i) cp_async16(sB1[s] + offB[i], pB1[i] + s * BK);
#pragma unroll
        for (int i = 0; i < 2; ++i) cp_async16(sB3[s] + offB[i], pB3[i] + s * BK);
        cp_async_commit();
    }
#pragma unroll
    for (int i = 0; i < 4; ++i) pA[i] += (STAGES - 1) * BK;
#pragma unroll
    for (int i = 0; i < 2; ++i) { pB1[i] += (STAGES - 1) * BK; pB3[i] += (STAGES - 1) * BK; }

    float acc1[4][2][4], acc3[4][2][4];
#pragma unroll
    for (int i = 0; i < 4; ++i)
#pragma unroll
        for (int j = 0; j < 2; ++j)
#pragma unroll
            for (int q = 0; q < 4; ++q) { acc1[i][j][q] = 0.f; acc3[i][j][q] = 0.f; }

    const int a_row = wm + ((lane >> 3) & 1) * 8 + (lane & 7);
    const int a_kb  = ((lane >> 4) & 1) * 16;
    const int b_row = wn + ((lane >> 4) & 1) * 8 + (lane & 7);
    const int b_kb  = ((lane >> 3) & 1) * 16;

    // swizzled ldsm offsets: addr(ks) = addr(0) ^ (ks*32)
    const uint32_t t_a = (uint32_t)(a_row & 7) << 4;
    const uint32_t t_b = (uint32_t)(b_row & 7) << 4;
    uint32_t asw[4];
#pragma unroll
    for (int im = 0; im < 4; ++im)
        asw[im] = (uint32_t)((a_row + im * 16) * 128) + ((uint32_t)a_kb ^ t_a);
    const uint32_t bsw = (uint32_t)(b_row * 128) + ((uint32_t)b_kb ^ t_b);

    for (int kt = 0; kt < KT; ++kt) {
        cp_async_wait<STAGES - 2>();   // stage kt%S ready
        __syncthreads();               // all warps done computing kt-1
        if (kt + STAGES - 1 < KT) {    // prefetch into just-freed stage
            const int sbuf = (kt + STAGES - 1) % STAGES;
#pragma unroll
            for (int i = 0; i < 4; ++i) cp_async16(sA[sbuf] + offA[i], pA[i]);
#pragma unroll
            for (int i = 0; i < 2; ++i) cp_async16(sB1[sbuf] + offB[i], pB1[i]);
#pragma unroll
            for (int i = 0; i < 2; ++i) cp_async16(sB3[sbuf] + offB[i], pB3[i]);
        }
        cp_async_commit();
#pragma unroll
        for (int i = 0; i < 4; ++i) pA[i] += BK;
#pragma unroll
        for (int i = 0; i < 2; ++i) { pB1[i] += BK; pB3[i] += BK; }

        const int st = kt % STAGES;
        uint32_t aoff[4];
#pragma unroll
        for (int im = 0; im < 4; ++im) aoff[im] = sA[st] + asw[im];
        const uint32_t b1off = sB1[st] + bsw;
        const uint32_t b3off = sB3[st] + bsw;

#pragma unroll
        for (int ks = 0; ks < 4; ++ks) {
            const uint32_t kx = (uint32_t)(ks * 32);
            uint32_t af[4][4], b1f[4], b3f[4];
            ldsm_x4(b1f, b1off ^ kx);
            ldsm_x4(b3f, b3off ^ kx);
#pragma unroll
            for (int im = 0; im < 4; ++im)
                ldsm_x4(af[im], aoff[im] ^ kx);
#pragma unroll
            for (int im = 0; im < 4; ++im) {
                mma16816(acc1[im][0], af[im], &b1f[0]);
                mma16816(acc1[im][1], af[im], &b1f[2]);
                mma16816(acc3[im][0], af[im], &b3f[0]);
                mma16816(acc3[im][1], af[im], &b3f[2]);
            }
        }
    }
    cp_async_wait<0>();

    // epilogue: h = silu(g1) * g3, fp16
    const int er = lane >> 2;
    const int ec = (lane & 3) * 2;
#pragma unroll
    for (int im = 0; im < 4; ++im) {
#pragma unroll
        for (int jn = 0; jn < 2; ++jn) {
            const float* c1 = acc1[im][jn];
            const float* c3 = acc3[im][jn];
            int gm = row0 + wm + im * 16 + er;
            int gn = col0 + wn + jn * 8 + ec;
            float h0 = (c1[0] / (1.f + __expf(-c1[0]))) * c3[0];
            float h1 = (c1[1] / (1.f + __expf(-c1[1]))) * c3[1];
            float h2 = (c1[2] / (1.f + __expf(-c1[2]))) * c3[2];
            float h3 = (c1[3] / (1.f + __expf(-c1[3]))) * c3[3];
            *reinterpret_cast<__half2*>(H + (size_t)gm * HID + gn) =
                __floats2half2_rn(h0, h1);
            *reinterpret_cast<__half2*>(H + (size_t)(gm + 8) * HID + gn) =
                __floats2half2_rn(h2, h3);
        }
    }
}

// ---------------------------------------------------------------------------
// GEMM2 (split-K=2): both splits red.global.add into C (zeroed beforehand).
// CTA 128x128; 8 warps (2m x 4n), warp tile 64x32. 2 CTAs/SM. Grouped G=16.
// ---------------------------------------------------------------------------
__global__ void __launch_bounds__(THREADS, 2)
gemm2_kernel(const __half* __restrict__ A, const __half* __restrict__ B,
             float* __restrict__ C) {
    extern __shared__ __align__(1024) char smem[];
    const int tid = threadIdx.x;
    const int wid = tid >> 5, lane = tid & 31;
    const uint32_t sb = smem_u32(smem);

    const int TN = DIM / G_BN;    // 32
    const int G = 16;
    const int bid = blockIdx.x;
    const int group = bid / (G * TN);
    const int rem = bid - group * (G * TN);
    const int bm = group * G + (rem % G);
    const int bn = rem / G;
    const int row0 = bm * G_BM, col0 = bn * G_BN;

    const int KT_ALL = HID / BK;                 // 172
    const int KT_HALF = KT_ALL / G_SPLITK;       // 86
    const int kt0 = blockIdx.y * KT_HALF;
    const int kt1 = kt0 + KT_HALF;

    const int wm = (wid & 1) * 64;
    const int wn = (wid >> 1) * 32;

    uint32_t sA[STAGES], sB[STAGES];
#pragma unroll
    for (int s = 0; s < STAGES; ++s) {
        sA[s] = sb + s * G_STAGE;
        sB[s] = sA[s] + G_BM * 128;
    }

    // precomputed chunk descriptors: A 4 chunks, B 4 chunks per thread
    uint32_t offA[4], offB[4];
    const __half *pA[4], *pB[4];
#pragma unroll
    for (int i = 0; i < 4; ++i) {
        int c = tid + i * THREADS;
        int r = c >> 3, cc = c & 7;
        uint32_t o = sw128((uint32_t)(r * 128 + cc * 16));
        offA[i] = o; offB[i] = o;
        pA[i] = A + (size_t)(row0 + r) * HID + kt0 * BK + cc * 8;
        pB[i] = B + (size_t)(col0 + r) * HID + kt0 * BK + cc * 8;
    }

#pragma unroll
    for (int s = 0; s < STAGES - 1; ++s) {
#pragma unroll
        for (int i = 0; i < 4; ++i) cp_async16(sA[s] + offA[i], pA[i] + s * BK);
#pragma unroll
        for (int i = 0; i < 4; ++i) cp_async16(sB[s] + offB[i], pB[i] + s * BK);
        cp_async_commit();
    }
#pragma unroll
    for (int i = 0; i < 4; ++i) { pA[i] += (STAGES - 1) * BK; pB[i] += (STAGES - 1) * BK; }

    float acc[4][4][4];
#pragma unroll
    for (int i = 0; i < 4; ++i)
#pragma unroll
        for (int j = 0; j < 4; ++j)
#pragma unroll
            for (int q = 0; q < 4; ++q) acc[i][j][q] = 0.f;

    const int a_row = wm + ((lane >> 3) & 1) * 8 + (lane & 7);
    const int a_kb  = ((lane >> 4) & 1) * 16;
    const int b_row = wn + ((lane >> 4) & 1) * 8 + (lane & 7);
    const int b_kb  = ((lane >> 3) & 1) * 16;

    const uint32_t t_a = (uint32_t)(a_row & 7) << 4;
    const uint32_t t_b = (uint32_t)(b_row & 7) << 4;
    uint32_t asw[4];
#pragma unroll
    for (int im = 0; im < 4; ++im)
        asw[im] = (uint32_t)((a_row + im * 16) * 128) + ((uint32_t)a_kb ^ t_a);
    uint32_t bswr[2];
#pragma unroll
    for (int j16 = 0; j16 < 2; ++j16)
        bswr[j16] = (uint32_t)((b_row + j16 * 16) * 128) + ((uint32_t)b_kb ^ t_b);

    for (int kt = kt0; kt < kt1; ++kt) {
        cp_async_wait<STAGES - 2>();
        __syncthreads();
        if (kt + STAGES - 1 < kt1) {
            const int sbuf = (kt + STAGES - 1 - kt0) % STAGES;
#pragma unroll
            for (int i = 0; i < 4; ++i) cp_async16(sA[sbuf] + offA[i], pA[i]);
#pragma unroll
            for (int i = 0; i < 4; ++i) cp_async16(sB[sbuf] + offB[i], pB[i]);
        }
        cp_async_commit();
#pragma unroll
        for (int i = 0; i < 4; ++i) { pA[i] += BK; pB[i] += BK; }

        const int st = (kt - kt0) % STAGES;
        uint32_t aoff[4];
#pragma unroll
        for (int im = 0; im < 4; ++im) aoff[im] = sA[st] + asw[im];
        uint32_t boff[2];
#pragma unroll
        for (int j16 = 0; j16 < 2; ++j16) boff[j16] = sB[st] + bswr[j16];

#pragma unroll
        for (int ks = 0; ks < 4; ++ks) {
            const uint32_t kx = (uint32_t)(ks * 32);
            uint32_t af[4][4], bf[2][4];
#pragma unroll
            for (int j16 = 0; j16 < 2; ++j16)
                ldsm_x4(bf[j16], boff[j16] ^ kx);
#pragma unroll
            for (int im = 0; im < 4; ++im)
                ldsm_x4(af[im], aoff[im] ^ kx);
#pragma unroll
            for (int im = 0; im < 4; ++im)
#pragma unroll
                for (int j16 = 0; j16 < 2; ++j16) {
                    mma16816(acc[im][2 * j16],     af[im], &bf[j16][0]);
                    mma16816(acc[im][2 * j16 + 1], af[im], &bf[j16][2]);
                }
        }
    }
    cp_async_wait<0>();

    // epilogue: red.global accumulate (atomicAdd with unused result -> RED)
    const int er = lane >> 2;
    const int ec = (lane & 3) * 2;
#pragma unroll
    for (int im = 0; im < 4; ++im) {
#pragma unroll
        for (int jn = 0; jn < 4; ++jn) {
            const float* c = acc[im][jn];
            int gm = row0 + wm + im * 16 + er;
            int gn = col0 + wn + jn * 8 + ec;
            atomicAdd(C + (size_t)gm * DIM + gn,     c[0]);
            atomicAdd(C + (size_t)gm * DIM + gn + 1, c[1]);
            atomicAdd(C + (size_t)(gm + 8) * DIM + gn,     c[2]);
            atomicAdd(C + (size_t)(gm + 8) * DIM + gn + 1, c[3]);
        }
    }
}

// ---------------------------------------------------------------------------
// Host launcher. Two-phase side-stream overlap; zero_out hidden under fused.
// ---------------------------------------------------------------------------
extern "C" void kernel_launch(void* const* d_in, const int* in_sizes, int n_in,
                              void* d_out, int out_size) {
    (void)in_sizes; (void)n_in;
    const float* x   = (const float*)d_in[0];
    const int*   w1c = (const int*)d_in[1];
    const float* w1a = (const float*)d_in[2];
    const int*   w2c = (const int*)d_in[3];
    const float* w2a = (const float*)d_in[4];
    const int*   w3c = (const int*)d_in[5];
    const float* w3a = (const float*)d_in[6];
    float* out = (float*)d_out;

    __half *pw1, *pw2, *pw3, *px, *ph;
    cudaGetSymbolAddress((void**)&pw1, g_w1);
    cudaGetSymbolAddress((void**)&pw2, g_w2);
    cudaGetSymbolAddress((void**)&pw3, g_w3);
    cudaGetSymbolAddress((void**)&px,  g_x);
    cudaGetSymbolAddress((void**)&ph,  g_h);

    cudaFuncSetAttribute(fused_gemm13_kernel,
                         cudaFuncAttributeMaxDynamicSharedMemorySize, F_SMEM);
    cudaFuncSetAttribute(gemm2_kernel,
                         cudaFuncAttributeMaxDynamicSharedMemorySize, G_SMEM);

    const int totalW = HID * DIM;          // 45,088,768
    const int wBlocks = totalW / 32 / 256; // 32 codes per thread, exact
    const int totalX = MTOK * DIM;

    cudaStream_t side;
    cudaStreamCreateWithFlags(&side, cudaStreamNonBlocking);
    cudaEvent_t evFork1, evJoin1, evFork2, evJoin2;
    cudaEventCreateWithFlags(&evFork1, cudaEventDisableTiming);
    cudaEventCreateWithFlags(&evJoin1, cudaEventDisableTiming);
    cudaEventCreateWithFlags(&evFork2, cudaEventDisableTiming);
    cudaEventCreateWithFlags(&evJoin2, cudaEventDisableTiming);

    // Phase 1: dq(W3) on side  ||  convert_x + dq(W1) on main
    cudaEventRecord(evFork1, 0);
    cudaStreamWaitEvent(side, evFork1, 0);
    dequant_nf4_kernel<DIM><<<wBlocks, 256, 0, side>>>(w3c, w3a, pw3, totalW);
    cudaEventRecord(evJoin1, side);

    convert_x_kernel<<<totalX / 8 / 256, 256>>>(x, px, totalX);
    dequant_nf4_kernel<DIM><<<wBlocks, 256>>>(w1c, w1a, pw1, totalW);
    cudaStreamWaitEvent(0, evJoin1, 0);

    // Phase 2 fork BEFORE the fused launch: dq(W2) + zero(out) overlap the GEMM.
    cudaEventRecord(evFork2, 0);
    cudaStreamWaitEvent(side, evFork2, 0);
    dequant_nf4_kernel<HID><<<wBlocks, 256, 0, side>>>(w2c, w2a, pw2, totalW);
    zero_out_kernel<<<(out_size / 4 + 255) / 256, 256, 0, side>>>(
        (float4*)out, out_size / 4);
    cudaEventRecord(evJoin2, side);

    // H = silu(x W1^T) * (x W3^T)
    {
        const int TM = MTOK / F_BM;   // 32
        const int TN = HID / F_BN;    // 172
        fused_gemm13_kernel<<<TM * TN, THREADS, F_SMEM>>>(px, pw1, pw3, ph);
    }

    // Join, then out += H W2^T (split-K via RED)
    cudaStreamWaitEvent(0, evJoin2, 0);
    {
        const int TM = MTOK / G_BM;   // 32
        const int TN = DIM / G_BN;    // 32
        gemm2_kernel<<<dim3(TM * TN, G_SPLITK), THREADS, G_SMEM>>>(ph, pw2, out);
    }
}

// round 15
// speedup vs baseline: 1.0455x; 1.0252x over previous
#include <cuda_runtime.h>
#include <cuda_fp16.h>
#include <cstdint>
#include <cstddef>

// ---------------------------------------------------------------------------
// Problem constants
// ---------------------------------------------------------------------------
#define DIM   4096
#define HID   11008
#define MTOK  4096          // B*S = 2*2048

static constexpr int BK = 64;          // 64 fp16 = 128 bytes per row (SW128 atom)
static constexpr int THREADS = 256;    // 8 warps
static constexpr int STAGES = 3;

// Fused GEMM1+3: CTA 128(m) x 64(n per matrix); stage = A 16K + B1 8K + B3 8K
static constexpr int F_BM = 128;
static constexpr int F_BN = 64;                         // per weight matrix
static constexpr int F_STAGE = (F_BM + 2 * F_BN) * 128; // 32 KB
static constexpr int F_SMEM = STAGES * F_STAGE;         // 96 KB

// GEMM2: CTA 128 x 128, split-K = 2
static constexpr int G_BM = 128;
static constexpr int G_BN = 128;
static constexpr int G_SPLITK = 2;
static constexpr int G_STAGE = (G_BM + G_BN) * 128;     // 32 KB
static constexpr int G_SMEM = STAGES * G_STAGE;         // 96 KB

// ---------------------------------------------------------------------------
// NF4 codebook
// ---------------------------------------------------------------------------
__constant__ float c_nf4[16] = {
    -1.0f, -0.6961928009986877f, -0.5250730514526367f, -0.39491748809814453f,
    -0.28444138169288635f, -0.18477343022823334f, -0.09105003625154495f, 0.0f,
    0.07958029955625534f, 0.16093020141124725f, 0.24611230194568634f,
    0.33791524171829224f, 0.44070982933044434f, 0.5626170039176941f,
    0.6989939212799072f, 1.0f};

// ---------------------------------------------------------------------------
// Static device scratch
// ---------------------------------------------------------------------------
__device__ __align__(256) __half g_w1[(size_t)HID * DIM];
__device__ __align__(256) __half g_w3[(size_t)HID * DIM];
__device__ __align__(256) __half g_w2[(size_t)DIM * HID];
__device__ __align__(256) __half g_x [(size_t)MTOK * DIM];
__device__ __align__(256) __half g_h [(size_t)MTOK * HID];

// ---------------------------------------------------------------------------
// PTX helpers (sm_100 baseline: cp.async, ldmatrix, mma.sync)
// ---------------------------------------------------------------------------
__device__ __forceinline__ uint32_t smem_u32(const void* p) {
    uint32_t r;
    asm("{ .reg .u64 t; cvta.to.shared.u64 t, %1; cvt.u32.u64 %0, t; }"
        : "=r"(r) : "l"(p));
    return r;
}

__device__ __forceinline__ void cp_async16(uint32_t dst, const void* src) {
    asm volatile("cp.async.cg.shared.global [%0], [%1], 16;" :: "r"(dst), "l"(src));
}
__device__ __forceinline__ void cp_async_commit() {
    asm volatile("cp.async.commit_group;" ::: "memory");
}
template <int N>
__device__ __forceinline__ void cp_async_wait() {
    asm volatile("cp.async.wait_group %0;" :: "n"(N) : "memory");
}

__device__ __forceinline__ void ldsm_x4(uint32_t* r, uint32_t addr) {
    asm volatile("ldmatrix.sync.aligned.m8n8.x4.shared.b16 {%0,%1,%2,%3}, [%4];"
                 : "=r"(r[0]), "=r"(r[1]), "=r"(r[2]), "=r"(r[3]) : "r"(addr));
}

__device__ __forceinline__ void mma16816(float* c, const uint32_t* a, const uint32_t* b) {
    asm volatile(
        "mma.sync.aligned.m16n8k16.row.col.f32.f16.f16.f32 "
        "{%0,%1,%2,%3}, {%4,%5,%6,%7}, {%8,%9}, {%0,%1,%2,%3};"
        : "+f"(c[0]), "+f"(c[1]), "+f"(c[2]), "+f"(c[3])
        : "r"(a[0]), "r"(a[1]), "r"(a[2]), "r"(a[3]), "r"(b[0]), "r"(b[1]));
}

__device__ __forceinline__ uint32_t sw128(uint32_t off) {
    return off ^ ((off >> 3) & 0x70);
}

// ---------------------------------------------------------------------------
// Dequant (coalesced layout + shfl-LUT) / convert / zero kernels
// Each thread handles 4 consecutive codes per iteration, 8 iterations;
// warp accesses are contiguous (4 lines per LDG, coalesced stores).
// ---------------------------------------------------------------------------
template <int K>
__global__ void __launch_bounds__(256)
dequant_nf4_kernel(const int* __restrict__ codes, const float* __restrict__ absmax,
                   __half* __restrict__ out, int total) {
    const int tid = threadIdx.x;
    // Register LUT: lane i holds nf4[i & 15]; lookup via one shfl.
    const float tbl = c_nf4[tid & 15];
    const int blockBase = blockIdx.x * (256 * 32);   // 8192 codes per block
    if (blockBase >= total) return;

#pragma unroll
    for (int i = 0; i < 8; ++i) {
        const int idx = blockBase + (i * 256 + tid) * 4;   // 4 consecutive codes
        int4 c = *reinterpret_cast<const int4*>(codes + idx);
        // 4-elem group lies within one 64-wide absmax block (K % 4 == 0).
        const int row = idx / K;                  // K is compile-time
        const int col = idx - row * K;
        const float am = absmax[row * (K >> 6) + (col >> 6)];

        float v0 = __shfl_sync(0xffffffffu, tbl, c.x & 15);
        float v1 = __shfl_sync(0xffffffffu, tbl, c.y & 15);
        float v2 = __shfl_sync(0xffffffffu, tbl, c.z & 15);
        float v3 = __shfl_sync(0xffffffffu, tbl, c.w & 15);
        __half2 h0 = __floats2half2_rn(v0 * am, v1 * am);
        __half2 h1 = __floats2half2_rn(v2 * am, v3 * am);
        uint2 pk;
        pk.x = *reinterpret_cast<uint32_t*>(&h0);
        pk.y = *reinterpret_cast<uint32_t*>(&h1);
        *reinterpret_cast<uint2*>(out + idx) = pk;
    }
}

__global__ void __launch_bounds__(256)
convert_x_kernel(const float* __restrict__ x, __half* __restrict__ out, int total) {
    int t = blockIdx.x * 256 + threadIdx.x;
    int base = t * 8;
    if (base >= total) return;
    float4 a = reinterpret_cast<const float4*>(x + base)[0];
    float4 b = reinterpret_cast<const float4*>(x + base)[1];
    __half2 hs[4];
    hs[0] = __floats2half2_rn(a.x, a.y);
    hs[1] = __floats2half2_rn(a.z, a.w);
    hs[2] = __floats2half2_rn(b.x, b.y);
    hs[3] = __floats2half2_rn(b.z, b.w);
    *reinterpret_cast<uint4*>(out + base) = *reinterpret_cast<const uint4*>(hs);
}

__global__ void __launch_bounds__(256)
zero_out_kernel(float4* __restrict__ p, int total4) {
    int t = blockIdx.x * 256 + threadIdx.x;
    if (t < total4) p[t] = make_float4(0.f, 0.f, 0.f, 0.f);
}

// ---------------------------------------------------------------------------
// Fused GEMM1+GEMM3+SwiGLU:  H = silu(x W1^T) * (x W3^T), fp16 out.
// CTA 128m x 64n per matrix; 8 warps (2m x 4n), warp tile 64m x 16n/matrix.
// 3-stage cp.async pipeline, one __syncthreads per k-tile, 2 CTAs/SM.
// Grouped raster G=16 (measured optimum).
// ---------------------------------------------------------------------------
__global__ void __launch_bounds__(THREADS, 2)
fused_gemm13_kernel(const __half* __restrict__ A, const __half* __restrict__ B1,
                    const __half* __restrict__ B3, __half* __restrict__ H) {
    extern __shared__ __align__(1024) char smem[];
    const int tid = threadIdx.x;
    const int wid = tid >> 5, lane = tid & 31;
    const uint32_t sb = smem_u32(smem);

    // grouped raster: groups of G m-tiles sweep all n-tiles
    const int TN = HID / F_BN;   // 172
    const int G = 16;
    const int bid = blockIdx.x;
    const int group = bid / (G * TN);
    const int rem = bid - group * (G * TN);
    const int bm = group * G + (rem % G);
    const int bn = rem / G;
    const int row0 = bm * F_BM, col0 = bn * F_BN;

    const int wm = (wid & 1) * 64;       // warp m offset
    const int wn = (wid >> 1) * 16;      // warp n offset (per weight matrix)

    uint32_t sA[STAGES], sB1[STAGES], sB3[STAGES];
#pragma unroll
    for (int s = 0; s < STAGES; ++s) {
        sA[s]  = sb + s * F_STAGE;
        sB1[s] = sA[s] + F_BM * 128;
        sB3[s] = sB1[s] + F_BN * 128;
    }

    // ---- precomputed cp.async chunk descriptors (loop-invariant) ----
    uint32_t offA[4], offB[2];
    const __half *pA[4], *pB1[2], *pB3[2];
#pragma unroll
    for (int i = 0; i < 4; ++i) {
        int c = tid + i * THREADS;
        int r = c >> 3, cc = c & 7;
        offA[i] = sw128((uint32_t)(r * 128 + cc * 16));
        pA[i] = A + (size_t)(row0 + r) * DIM + cc * 8;
    }
#pragma unroll
    for (int i = 0; i < 2; ++i) {
        int c = tid + i * THREADS;
        int r = c >> 3, cc = c & 7;
        offB[i] = sw128((uint32_t)(r * 128 + cc * 16));
        pB1[i] = B1 + (size_t)(col0 + r) * DIM + cc * 8;
        pB3[i] = B3 + (size_t)(col0 + r) * DIM + cc * 8;
    }

    const int KT = DIM / BK;    // 64

    // prologue: stages 0..STAGES-2
#pragma unroll
    for (int s = 0; s < STAGES - 1; ++s) {
#pragma unroll
        for (int i = 0; i < 4; ++i) cp_async16(sA[s] + offA[i], pA[i] + s * BK);
#pragma unroll
        for (int i = 0; i < 2; ++i) cp_async16(sB1[s] + offB[i], pB1[i] + s * BK);
#pragma unroll
        for (int i = 0; i < 2; ++i) cp_async16(sB3[s] + offB[i], pB3[i] + s * BK);
        cp_async_commit();
    }
#pragma unroll
    for (int i = 0; i < 4; ++i) pA[i] += (STAGES - 1) * BK;
#pragma unroll
    for (int i = 0; i < 2; ++i) { pB1[i] += (STAGES - 1) * BK; pB3[i] += (STAGES - 1) * BK; }

    float acc1[4][2][4], acc3[4][2][4];
#pragma unroll
    for (int i = 0; i < 4; ++i)
#pragma unroll
        for (int j = 0; j < 2; ++j)
#pragma unroll
            for (int q = 0; q < 4; ++q) { acc1[i][j][q] = 0.f; acc3[i][j][q] = 0.f; }

    const int a_row = wm + ((lane >> 3) & 1) * 8 + (lane & 7);
    const int a_kb  = ((lane >> 4) & 1) * 16;
    const int b_row = wn + ((lane >> 4) & 1) * 8 + (lane & 7);
    const int b_kb  = ((lane >> 3) & 1) * 16;

    // swizzled ldsm offsets: addr(ks) = addr(0) ^ (ks*32)
    const uint32_t t_a = (uint32_t)(a_row & 7) << 4;
    const uint32_t t_b = (uint32_t)(b_row & 7) << 4;
    uint32_t asw[4];
#pragma unroll
    for (int im = 0; im < 4; ++im)
        asw[im] = (uint32_t)((a_row + im * 16) * 128) + ((uint32_t)a_kb ^ t_a);
    const uint32_t bsw = (uint32_t)(b_row * 128) + ((uint32_t)b_kb ^ t_b);

    for (int kt = 0; kt < KT; ++kt) {
        cp_async_wait<STAGES - 2>();   // stage kt%S ready
        __syncthreads();               // all warps done computing kt-1
        if (kt + STAGES - 1 < KT) {    // prefetch into just-freed stage
            const int sbuf = (kt + STAGES - 1) % STAGES;
#pragma unroll
            for (int i = 0; i < 4; ++i) cp_async16(sA[sbuf] + offA[i], pA[i]);
#pragma unroll
            for (int i = 0; i < 2; ++i) cp_async16(sB1[sbuf] + offB[i], pB1[i]);
#pragma unroll
            for (int i = 0; i < 2; ++i) cp_async16(sB3[sbuf] + offB[i], pB3[i]);
        }
        cp_async_commit();
#pragma unroll
        for (int i = 0; i < 4; ++i) pA[i] += BK;
#pragma unroll
        for (int i = 0; i < 2; ++i) { pB1[i] += BK; pB3[i] += BK; }

        const int st = kt % STAGES;
        uint32_t aoff[4];
#pragma unroll
        for (int im = 0; im < 4; ++im) aoff[im] = sA[st] + asw[im];
        const uint32_t b1off = sB1[st] + bsw;
        const uint32_t b3off = sB3[st] + bsw;

#pragma unroll
        for (int ks = 0; ks < 4; ++ks) {
            const uint32_t kx = (uint32_t)(ks * 32);
            uint32_t af[4][4], b1f[4], b3f[4];
            ldsm_x4(b1f, b1off ^ kx);
            ldsm_x4(b3f, b3off ^ kx);
#pragma unroll
            for (int im = 0; im < 4; ++im)
                ldsm_x4(af[im], aoff[im] ^ kx);
#pragma unroll
            for (int im = 0; im < 4; ++im) {
                mma16816(acc1[im][0], af[im], &b1f[0]);
                mma16816(acc1[im][1], af[im], &b1f[2]);
                mma16816(acc3[im][0], af[im], &b3f[0]);
                mma16816(acc3[im][1], af[im], &b3f[2]);
            }
        }
    }
    cp_async_wait<0>();

    // epilogue: h = silu(g1) * g3, fp16
    const int er = lane >> 2;
    const int ec = (lane & 3) * 2;
#pragma unroll
    for (int im = 0; im < 4; ++im) {
#pragma unroll
        for (int jn = 0; jn < 2; ++jn) {
            const float* c1 = acc1[im][jn];
            const float* c3 = acc3[im][jn];
            int gm = row0 + wm + im * 16 + er;
            int gn = col0 + wn + jn * 8 + ec;
            float h0 = (c1[0] / (1.f + __expf(-c1[0]))) * c3[0];
            float h1 = (c1[1] / (1.f + __expf(-c1[1]))) * c3[1];
            float h2 = (c1[2] / (1.f + __expf(-c1[2]))) * c3[2];
            float h3 = (c1[3] / (1.f + __expf(-c1[3]))) * c3[3];
            *reinterpret_cast<__half2*>(H + (size_t)gm * HID + gn) =
                __floats2half2_rn(h0, h1);
            *reinterpret_cast<__half2*>(H + (size_t)(gm + 8) * HID + gn) =
                __floats2half2_rn(h2, h3);
        }
    }
}

// ---------------------------------------------------------------------------
// GEMM2 (split-K=2): both splits red.global.add into C (zeroed beforehand).
// CTA 128x128; 8 warps (2m x 4n), warp tile 64x32. 2 CTAs/SM. Grouped G=16.
// ---------------------------------------------------------------------------
__global__ void __launch_bounds__(THREADS, 2)
gemm2_kernel(const __half* __restrict__ A, const __half* __restrict__ B,
             float* __restrict__ C) {
    extern __shared__ __align__(1024) char smem[];
    const int tid = threadIdx.x;
    const int wid = tid >> 5, lane = tid & 31;
    const uint32_t sb = smem_u32(smem);

    const int TN = DIM / G_BN;    // 32
    const int G = 16;
    const int bid = blockIdx.x;
    const int group = bid / (G * TN);
    const int rem = bid - group * (G * TN);
    const int bm = group * G + (rem % G);
    const int bn = rem / G;
    const int row0 = bm * G_BM, col0 = bn * G_BN;

    const int KT_ALL = HID / BK;                 // 172
    const int KT_HALF = KT_ALL / G_SPLITK;       // 86
    const int kt0 = blockIdx.y * KT_HALF;
    const int kt1 = kt0 + KT_HALF;

    const int wm = (wid & 1) * 64;
    const int wn = (wid >> 1) * 32;

    uint32_t sA[STAGES], sB[STAGES];
#pragma unroll
    for (int s = 0; s < STAGES; ++s) {
        sA[s] = sb + s * G_STAGE;
        sB[s] = sA[s] + G_BM * 128;
    }

    // precomputed chunk descriptors: A 4 chunks, B 4 chunks per thread
    uint32_t offA[4], offB[4];
    const __half *pA[4], *pB[4];
#pragma unroll
    for (int i = 0; i < 4; ++i) {
        int c = tid + i * THREADS;
        int r = c >> 3, cc = c & 7;
        uint32_t o = sw128((uint32_t)(r * 128 + cc * 16));
        offA[i] = o; offB[i] = o;
        pA[i] = A + (size_t)(row0 + r) * HID + kt0 * BK + cc * 8;
        pB[i] = B + (size_t)(col0 + r) * HID + kt0 * BK + cc * 8;
    }

#pragma unroll
    for (int s = 0; s < STAGES - 1; ++s) {
#pragma unroll
        for (int i = 0; i < 4; ++i) cp_async16(sA[s] + offA[i], pA[i] + s * BK);
#pragma unroll
        for (int i = 0; i < 4; ++i) cp_async16(sB[s] + offB[i], pB[i] + s * BK);
        cp_async_commit();
    }
#pragma unroll
    for (int i = 0; i < 4; ++i) { pA[i] += (STAGES - 1) * BK; pB[i] += (STAGES - 1) * BK; }

    float acc[4][4][4];
#pragma unroll
    for (int i = 0; i < 4; ++i)
#pragma unroll
        for (int j = 0; j < 4; ++j)
#pragma unroll
            for (int q = 0; q < 4; ++q) acc[i][j][q] = 0.f;

    const int a_row = wm + ((lane >> 3) & 1) * 8 + (lane & 7);
    const int a_kb  = ((lane >> 4) & 1) * 16;
    const int b_row = wn + ((lane >> 4) & 1) * 8 + (lane & 7);
    const int b_kb  = ((lane >> 3) & 1) * 16;

    const uint32_t t_a = (uint32_t)(a_row & 7) << 4;
    const uint32_t t_b = (uint32_t)(b_row & 7) << 4;
    uint32_t asw[4];
#pragma unroll
    for (int im = 0; im < 4; ++im)
        asw[im] = (uint32_t)((a_row + im * 16) * 128) + ((uint32_t)a_kb ^ t_a);
    uint32_t bswr[2];
#pragma unroll
    for (int j16 = 0; j16 < 2; ++j16)
        bswr[j16] = (uint32_t)((b_row + j16 * 16) * 128) + ((uint32_t)b_kb ^ t_b);

    for (int kt = kt0; kt < kt1; ++kt) {
        cp_async_wait<STAGES - 2>();
        __syncthreads();
        if (kt + STAGES - 1 < kt1) {
            const int sbuf = (kt + STAGES - 1 - kt0) % STAGES;
#pragma unroll
            for (int i = 0; i < 4; ++i) cp_async16(sA[sbuf] + offA[i], pA[i]);
#pragma unroll
            for (int i = 0; i < 4; ++i) cp_async16(sB[sbuf] + offB[i], pB[i]);
        }
        cp_async_commit();
#pragma unroll
        for (int i = 0; i < 4; ++i) { pA[i] += BK; pB[i] += BK; }

        const int st = (kt - kt0) % STAGES;
        uint32_t aoff[4];
#pragma unroll
        for (int im = 0; im < 4; ++im) aoff[im] = sA[st] + asw[im];
        uint32_t boff[2];
#pragma unroll
        for (int j16 = 0; j16 < 2; ++j16) boff[j16] = sB[st] + bswr[j16];

#pragma unroll
        for (int ks = 0; ks < 4; ++ks) {
            const uint32_t kx = (uint32_t)(ks * 32);
            uint32_t af[4][4], bf[2][4];
#pragma unroll
            for (int j16 = 0; j16 < 2; ++j16)
                ldsm_x4(bf[j16], boff[j16] ^ kx);
#pragma unroll
            for (int im = 0; im < 4; ++im)
                ldsm_x4(af[im], aoff[im] ^ kx);
#pragma unroll
            for (int im = 0; im < 4; ++im)
#pragma unroll
                for (int j16 = 0; j16 < 2; ++j16) {
                    mma16816(acc[im][2 * j16],     af[im], &bf[j16][0]);
                    mma16816(acc[im][2 * j16 + 1], af[im], &bf[j16][2]);
                }
        }
    }
    cp_async_wait<0>();

    // epilogue: red.global accumulate (atomicAdd with unused result -> RED)
    const int er = lane >> 2;
    const int ec = (lane & 3) * 2;
#pragma unroll
    for (int im = 0; im < 4; ++im) {
#pragma unroll
        for (int jn = 0; jn < 4; ++jn) {
            const float* c = acc[im][jn];
            int gm = row0 + wm + im * 16 + er;
            int gn = col0 + wn + jn * 8 + ec;
            atomicAdd(C + (size_t)gm * DIM + gn,     c[0]);
            atomicAdd(C + (size_t)gm * DIM + gn + 1, c[1]);
            atomicAdd(C + (size_t)(gm + 8) * DIM + gn,     c[2]);
            atomicAdd(C + (size_t)(gm + 8) * DIM + gn + 1, c[3]);
        }
    }
}

// ---------------------------------------------------------------------------
// Host launcher. Two-phase side-stream overlap; zero_out hidden under fused.
// ---------------------------------------------------------------------------
extern "C" void kernel_launch(void* const* d_in, const int* in_sizes, int n_in,
                              void* d_out, int out_size) {
    (void)in_sizes; (void)n_in;
    const float* x   = (const float*)d_in[0];
    const int*   w1c = (const int*)d_in[1];
    const float* w1a = (const float*)d_in[2];
    const int*   w2c = (const int*)d_in[3];
    const float* w2a = (const float*)d_in[4];
    const int*   w3c = (const int*)d_in[5];
    const float* w3a = (const float*)d_in[6];
    float* out = (float*)d_out;

    __half *pw1, *pw2, *pw3, *px, *ph;
    cudaGetSymbolAddress((void**)&pw1, g_w1);
    cudaGetSymbolAddress((void**)&pw2, g_w2);
    cudaGetSymbolAddress((void**)&pw3, g_w3);
    cudaGetSymbolAddress((void**)&px,  g_x);
    cudaGetSymbolAddress((void**)&ph,  g_h);

    cudaFuncSetAttribute(fused_gemm13_kernel,
                         cudaFuncAttributeMaxDynamicSharedMemorySize, F_SMEM);
    cudaFuncSetAttribute(gemm2_kernel,
                         cudaFuncAttributeMaxDynamicSharedMemorySize, G_SMEM);

    const int totalW = HID * DIM;          // 45,088,768
    const int wBlocks = totalW / 32 / 256; // 32 codes per thread, exact
    const int totalX = MTOK * DIM;

    cudaStream_t side;
    cudaStreamCreateWithFlags(&side, cudaStreamNonBlocking);
    cudaEvent_t evFork1, evJoin1, evFork2, evJoin2;
    cudaEventCreateWithFlags(&evFork1, cudaEventDisableTiming);
    cudaEventCreateWithFlags(&evJoin1, cudaEventDisableTiming);
    cudaEventCreateWithFlags(&evFork2, cudaEventDisableTiming);
    cudaEventCreateWithFlags(&evJoin2, cudaEventDisableTiming);

    // Phase 1: dq(W3) on side  ||  convert_x + dq(W1) on main
    cudaEventRecord(evFork1, 0);
    cudaStreamWaitEvent(side, evFork1, 0);
    dequant_nf4_kernel<DIM><<<wBlocks, 256, 0, side>>>(w3c, w3a, pw3, totalW);
    cudaEventRecord(evJoin1, side);

    convert_x_kernel<<<totalX / 8 / 256, 256>>>(x, px, totalX);
    dequant_nf4_kernel<DIM><<<wBlocks, 256>>>(w1c, w1a, pw1, totalW);
    cudaStreamWaitEvent(0, evJoin1, 0);

    // Phase 2 fork BEFORE the fused launch: dq(W2) + zero(out) overlap the GEMM.
    cudaEventRecord(evFork2, 0);
    cudaStreamWaitEvent(side, evFork2, 0);
    dequant_nf4_kernel<HID><<<wBlocks, 256, 0, side>>>(w2c, w2a, pw2, totalW);
    zero_out_kernel<<<(out_size / 4 + 255) / 256, 256, 0, side>>>(
        (float4*)out, out_size / 4);
    cudaEventRecord(evJoin2, side);

    // H = silu(x W1^T) * (x W3^T)
    {
        const int TM = MTOK / F_BM;   // 32
        const int TN = HID / F_BN;    // 172
        fused_gemm13_kernel<<<TM * TN, THREADS, F_SMEM>>>(px, pw1, pw3, ph);
    }

    // Join, then out += H W2^T (split-K via RED)
    cudaStreamWaitEvent(0, evJoin2, 0);
    {
        const int TM = MTOK / G_BM;   // 32
        const int TN = DIM / G_BN;    // 32
        gemm2_kernel<<<dim3(TM * TN, G_SPLITK), THREADS, G_SMEM>>>(ph, pw2, out);
    }
}